// round 3
// baseline (speedup 1.0000x reference)
#include <cuda_runtime.h>

#define B_   4
#define T_   2048
#define C_   1024
#define H_   16
#define D_   64
#define BT_  (B_*T_)

// Scratch (device globals are the sanctioned scratch mechanism)
__device__ __align__(16) float g_Q[BT_*C_];   // [B][H][T][64]
__device__ __align__(16) float g_K[BT_*C_];   // [B][H][T][64]
__device__ __align__(16) float g_V[BT_*C_];   // [B][H][T][64]
__device__ __align__(16) float g_O[BT_*C_];   // [B][T][C]

using ull = unsigned long long;

__device__ __forceinline__ void ffma2(ull &d, ull a, ull b) {
    asm("fma.rn.f32x2 %0, %1, %2, %3;" : "=l"(d) : "l"(a), "l"(b), "l"(d));
}
__device__ __forceinline__ void fmul2(ull &d, ull a, ull b) {
    asm("mul.rn.f32x2 %0, %1, %2;" : "=l"(d) : "l"(a), "l"(b));
}
__device__ __forceinline__ ull pack2(float x, float y) {
    ull r; asm("mov.b64 %0, {%1, %2};" : "=l"(r) : "f"(x), "f"(y)); return r;
}
__device__ __forceinline__ float2 unpack2(ull v) {
    float2 f; asm("mov.b64 {%0, %1}, %2;" : "=f"(f.x), "=f"(f.y) : "l"(v)); return f;
}
__device__ __forceinline__ ull d2u(double d) { return (ull)__double_as_longlong(d); }

// ---------------------------------------------------------------------------
// Register-blocked SGEMM, 128x128 tile, BK=8, 256 threads, f32x2 FMAs.
// MODE 0: C = x @ W_qkv + b_qkv, scattered into head-major g_Q/g_K/g_V
// MODE 1: C = g_O @ W_out + b_out, written to d_out
// K is always 1024. N_ is the template width of W.
// ---------------------------------------------------------------------------
template<int N_, int MODE>
__global__ __launch_bounds__(256) void gemm_kernel(
    const float* __restrict__ A, const float* __restrict__ W,
    const float* __restrict__ bias, float* __restrict__ Cout)
{
    __shared__ __align__(16) float As[8][132];   // [k][m], padded
    __shared__ __align__(16) float Bs[8][128];   // [k][n]

    const int tid = threadIdx.x;
    const int tx = tid & 15, ty = tid >> 4;
    const int bm = blockIdx.y * 128, bn = blockIdx.x * 128;

    const float* Abase = (MODE == 0) ? A : (const float*)g_O;

    const int arow = tid >> 1, akq = (tid & 1) * 4;   // A tile: 128 rows x 8 k
    const int brow = tid >> 5, bcol = (tid & 31) * 4; // B tile: 8 k x 128 cols

    const float* Ap = Abase + (bm + arow) * 1024 + akq;
    const float* Bp = W + brow * N_ + bn + bcol;

    float4 apre = *(const float4*)Ap;
    float4 bpre = *(const float4*)Bp;

    ull acc[8][4];
    #pragma unroll
    for (int i = 0; i < 8; i++)
        #pragma unroll
        for (int j = 0; j < 4; j++) acc[i][j] = 0ull;

    for (int k0 = 0; k0 < 1024; k0 += 8) {
        As[akq+0][arow] = apre.x;
        As[akq+1][arow] = apre.y;
        As[akq+2][arow] = apre.z;
        As[akq+3][arow] = apre.w;
        *(float4*)&Bs[brow][bcol] = bpre;
        __syncthreads();
        if (k0 + 8 < 1024) {
            apre = *(const float4*)(Ap + k0 + 8);
            bpre = *(const float4*)(Bp + (size_t)(k0 + 8) * N_);
        }
        #pragma unroll
        for (int k = 0; k < 8; k++) {
            float4 a0 = *(const float4*)&As[k][ty*4];
            float4 a1 = *(const float4*)&As[k][64 + ty*4];
            const double2* bd = (const double2*)&Bs[k][0];
            double2 bA = bd[tx];        // cols bn + tx*4 + {0,1,2,3}
            double2 bB = bd[16 + tx];   // cols bn + 64 + tx*4 + {0,1,2,3}
            ull b0 = d2u(bA.x), b1 = d2u(bA.y), b2 = d2u(bB.x), b3 = d2u(bB.y);
            float av[8] = {a0.x, a0.y, a0.z, a0.w, a1.x, a1.y, a1.z, a1.w};
            #pragma unroll
            for (int i = 0; i < 8; i++) {
                ull ad = pack2(av[i], av[i]);
                ffma2(acc[i][0], ad, b0);
                ffma2(acc[i][1], ad, b1);
                ffma2(acc[i][2], ad, b2);
                ffma2(acc[i][3], ad, b3);
            }
        }
        __syncthreads();
    }

    // Epilogue: add bias, scatter/store
    #pragma unroll
    for (int i = 0; i < 8; i++) {
        int m = bm + ((i < 4) ? (ty*4 + i) : (64 + ty*4 + (i - 4)));
        #pragma unroll
        for (int g = 0; g < 2; g++) {
            int n = bn + g*64 + tx*4;
            float2 p0 = unpack2(acc[i][g*2 + 0]);
            float2 p1 = unpack2(acc[i][g*2 + 1]);
            float4 v;
            v.x = p0.x + bias[n + 0];
            v.y = p0.y + bias[n + 1];
            v.z = p1.x + bias[n + 2];
            v.w = p1.y + bias[n + 3];
            if (MODE == 0) {
                int which = n >> 10;          // 0=Q 1=K 2=V
                int c = n & 1023;
                int h = c >> 6, d = c & 63;
                int bb = m >> 11, t = m & 2047;
                float* dst = (which == 0) ? g_Q : (which == 1) ? g_K : g_V;
                *(float4*)&dst[(((bb*H_ + h)*T_ + t)*D_ + d)] = v;
            } else {
                *(float4*)&Cout[(size_t)m * 1024 + n] = v;
            }
        }
    }
}

// ---------------------------------------------------------------------------
// Flash attention, fp32, causal. 128 queries per block (one per thread),
// key tiles of 32. K tile stored transposed in smem so key pairs are
// contiguous for f32x2; V tile row-major so d pairs are contiguous.
// ---------------------------------------------------------------------------
__global__ __launch_bounds__(128) void flash_kernel()
{
    __shared__ __align__(16) float smem[128 * 68];  // 34.8 KB, reused

    const int tid = threadIdx.x;
    const int qt = blockIdx.x, h = blockIdx.y, b = blockIdx.z;
    const int qbase = qt * 128;
    const int qi = qbase + tid;
    const float scale = 0.125f;   // 1/sqrt(64)

    const float* Qg  = g_Q + ((size_t)(b*H_ + h)*T_ + qbase) * D_;
    const float* Kg0 = g_K + ((size_t)(b*H_ + h)*T_) * D_;
    const float* Vg0 = g_V + ((size_t)(b*H_ + h)*T_) * D_;

    // Stage Q tile coalesced through smem, then into registers
    float* Qs = smem;   // stride 68
    #pragma unroll
    for (int i = 0; i < 16; i++) {
        int idx4 = tid + i*128;          // 0..2047 float4s
        int r = idx4 >> 4, d4 = (idx4 & 15) * 4;
        float4 v = *(const float4*)&Qg[r*64 + d4];
        *(float4*)&Qs[r*68 + d4] = v;
    }
    __syncthreads();
    float q[64];
    #pragma unroll
    for (int d = 0; d < 64; d++) q[d] = Qs[tid*68 + d];
    __syncthreads();

    float* Kst = smem;              // [64][36]  (transposed K, padded)
    float* Vs  = smem + 64*36;      // [32][64]

    float mrow = -1e30f, lrow = 0.f;
    ull o2[32];
    #pragma unroll
    for (int i = 0; i < 32; i++) o2[i] = 0ull;

    const int kend = qbase + 128;
    for (int kb = 0; kb < kend; kb += 32) {
        // Cooperative load: K transposed, V row-major
        #pragma unroll
        for (int i = 0; i < 4; i++) {
            int idx4 = tid + i*128;        // 0..511 float4s (32x64 tile)
            int j = idx4 >> 4, d4 = (idx4 & 15) * 4;
            float4 kv = *(const float4*)&Kg0[(size_t)(kb + j)*64 + d4];
            Kst[(d4+0)*36 + j] = kv.x;
            Kst[(d4+1)*36 + j] = kv.y;
            Kst[(d4+2)*36 + j] = kv.z;
            Kst[(d4+3)*36 + j] = kv.w;
            float4 vv = *(const float4*)&Vg0[(size_t)(kb + j)*64 + d4];
            *(float4*)&Vs[j*64 + d4] = vv;
        }
        __syncthreads();

        // S = q . K^T  (pairs of keys packed in f32x2)
        ull s2[16];
        #pragma unroll
        for (int jj = 0; jj < 16; jj++) s2[jj] = 0ull;
        #pragma unroll
        for (int d = 0; d < 64; d++) {
            ull qd = pack2(q[d], q[d]);
            const double2* kp = (const double2*)&Kst[d*36];  // 144d bytes, 16B aligned
            #pragma unroll
            for (int j4 = 0; j4 < 8; j4++) {
                double2 kk = kp[j4];
                ffma2(s2[2*j4 + 0], qd, d2u(kk.x));
                ffma2(s2[2*j4 + 1], qd, d2u(kk.y));
            }
        }

        float sv[32];
        #pragma unroll
        for (int jj = 0; jj < 16; jj++) {
            float2 p = unpack2(s2[jj]);
            sv[2*jj]     = p.x * scale;
            sv[2*jj + 1] = p.y * scale;
        }
        if (kb + 31 > qi) {
            #pragma unroll
            for (int j = 0; j < 32; j++)
                if (kb + j > qi) sv[j] = -1e30f;
        }

        float mt = mrow;
        #pragma unroll
        for (int j = 0; j < 32; j++) mt = fmaxf(mt, sv[j]);
        float alpha = __expf(mrow - mt);
        mrow = mt;
        lrow *= alpha;
        ull al = pack2(alpha, alpha);
        #pragma unroll
        for (int i = 0; i < 32; i++) fmul2(o2[i], o2[i], al);

        #pragma unroll
        for (int j = 0; j < 32; j++) {
            // guard: fully-masked rows keep p exactly 0 (avoids exp(0)=1 when m=-1e30)
            float p = (sv[j] > -1e29f) ? __expf(sv[j] - mrow) : 0.f;
            lrow += p;
            ull pd = pack2(p, p);
            const double2* vp = (const double2*)&Vs[j*64];
            #pragma unroll
            for (int d4 = 0; d4 < 16; d4++) {
                double2 vv = vp[d4];
                ffma2(o2[2*d4 + 0], pd, d2u(vv.x));
                ffma2(o2[2*d4 + 1], pd, d2u(vv.y));
            }
        }
        __syncthreads();
    }

    float inv = 1.f / lrow;
    float* Op = g_O + ((size_t)(b*T_ + qi)) * C_ + h*64;
    #pragma unroll
    for (int dd = 0; dd < 16; dd++) {
        float2 a = unpack2(o2[2*dd]);
        float2 c = unpack2(o2[2*dd + 1]);
        float4 v;
        v.x = a.x * inv; v.y = a.y * inv; v.z = c.x * inv; v.w = c.y * inv;
        *(float4*)&Op[dd*4] = v;
    }
}

extern "C" void kernel_launch(void* const* d_in, const int* in_sizes, int n_in,
                              void* d_out, int out_size) {
    const float* x    = (const float*)d_in[0];   // [4,2048,1024]
    const float* Wqkv = (const float*)d_in[1];   // [1024,3072]
    const float* bqkv = (const float*)d_in[2];   // [3072]
    const float* Wout = (const float*)d_in[3];   // [1024,1024]
    const float* bout = (const float*)d_in[4];   // [1024]
    float* out = (float*)d_out;                  // [4,2048,1024]

    // 1) QKV projection + bias + scatter to head-major Q/K/V
    gemm_kernel<3072, 0><<<dim3(24, 64), 256>>>(x, Wqkv, bqkv, nullptr);
    // 2) Causal flash attention -> g_O [B,T,C]
    flash_kernel<<<dim3(16, 16, 4), 128>>>();
    // 3) Output projection + bias -> d_out
    gemm_kernel<1024, 1><<<dim3(8, 64), 256>>>(nullptr, Wout, bout, out);
}

// round 7
// speedup vs baseline: 1.2334x; 1.2334x over previous
#include <cuda_runtime.h>
#include <cuda_bf16.h>
#include <cstdint>

#define B_   4
#define T_   2048
#define C_   1024
#define H_   16
#define D_   64
#define BT_  (B_*T_)
#define K3_  3072     // 3-segment split K: [hiA|loA|hiA] . [hiB|hiB|loB]

// ------------------------- scratch (device globals) -------------------------
__device__ __align__(16) float g_Q[BT_*C_];   // [B][H][T][64]
__device__ __align__(16) float g_K[BT_*C_];
__device__ __align__(16) float g_V[BT_*C_];
__device__ __align__(16) float g_O[BT_*C_];   // [B][T][C]
__device__ __align__(16) unsigned short g_A [BT_*K3_];      // x-split / O-split  [M][3072]
__device__ __align__(16) unsigned short g_Bq[3*C_*K3_];     // Wqkv^T split       [3072][3072]
__device__ __align__(16) unsigned short g_Bo[C_*K3_];       // Wout^T split       [1024][3072]

using ull = unsigned long long;

// ------------------------------ small helpers -------------------------------
__device__ __forceinline__ void ffma2(ull &d, ull a, ull b) {
    asm("fma.rn.f32x2 %0, %1, %2, %3;" : "=l"(d) : "l"(a), "l"(b), "l"(d));
}
__device__ __forceinline__ void fmul2(ull &d, ull a, ull b) {
    asm("mul.rn.f32x2 %0, %1, %2;" : "=l"(d) : "l"(a), "l"(b));
}
__device__ __forceinline__ ull pack2(float x, float y) {
    ull r; asm("mov.b64 %0, {%1, %2};" : "=l"(r) : "f"(x), "f"(y)); return r;
}
__device__ __forceinline__ float2 unpack2(ull v) {
    float2 f; asm("mov.b64 {%0, %1}, %2;" : "=f"(f.x), "=f"(f.y) : "l"(v)); return f;
}
__device__ __forceinline__ ull d2u(double d) { return (ull)__double_as_longlong(d); }

__device__ __forceinline__ uint32_t s2u(const void* p) {
    uint32_t a;
    asm("{ .reg .u64 t; cvta.to.shared.u64 t, %1; cvt.u32.u64 %0, t; }" : "=r"(a) : "l"(p));
    return a;
}
__device__ __forceinline__ void cp16(uint32_t d, const void* s) {
    asm volatile("cp.async.cg.shared.global [%0], [%1], 16;" :: "r"(d), "l"(s));
}
__device__ __forceinline__ void ldsm4(uint32_t& r0, uint32_t& r1, uint32_t& r2, uint32_t& r3,
                                      uint32_t a) {
    asm volatile("ldmatrix.sync.aligned.m8n8.x4.shared.b16 {%0,%1,%2,%3}, [%4];"
                 : "=r"(r0), "=r"(r1), "=r"(r2), "=r"(r3) : "r"(a));
}
__device__ __forceinline__ void mma16816(float* c, const uint32_t* a, const uint32_t* b) {
    asm volatile("mma.sync.aligned.m16n8k16.row.col.f32.bf16.bf16.f32 "
                 "{%0,%1,%2,%3}, {%4,%5,%6,%7}, {%8,%9}, {%0,%1,%2,%3};"
                 : "+f"(c[0]), "+f"(c[1]), "+f"(c[2]), "+f"(c[3])
                 : "r"(a[0]), "r"(a[1]), "r"(a[2]), "r"(a[3]), "r"(b[0]), "r"(b[1]));
}

// ------------------------------ prep kernels --------------------------------
// split fp32 [rows][1024] -> bf16 [rows][3072] = [hi | lo | hi]
__global__ __launch_bounds__(256) void prep_split_kernel(
    const float* __restrict__ src, unsigned short* __restrict__ dst)
{
    int idx = blockIdx.x * 256 + threadIdx.x;   // one float4 per thread
    int row = idx >> 8;                         // 256 float4 per row
    int c4  = idx & 255;
    float4 v = *(const float4*)(src + (size_t)row * 1024 + c4 * 4);
    float f[4] = {v.x, v.y, v.z, v.w};
    unsigned short h[4], l[4];
    #pragma unroll
    for (int i = 0; i < 4; i++) {
        __nv_bfloat16 hb = __float2bfloat16(f[i]);
        __nv_bfloat16 lb = __float2bfloat16(f[i] - __bfloat162float(hb));
        h[i] = __bfloat16_as_ushort(hb);
        l[i] = __bfloat16_as_ushort(lb);
    }
    uint64_t hp = (uint64_t)h[0] | ((uint64_t)h[1] << 16) | ((uint64_t)h[2] << 32) | ((uint64_t)h[3] << 48);
    uint64_t lp = (uint64_t)l[0] | ((uint64_t)l[1] << 16) | ((uint64_t)l[2] << 32) | ((uint64_t)l[3] << 48);
    unsigned short* rp = dst + (size_t)row * K3_ + c4 * 4;
    *(uint64_t*)(rp)        = hp;   // seg0: hi
    *(uint64_t*)(rp + 1024) = lp;   // seg1: lo
    *(uint64_t*)(rp + 2048) = hp;   // seg2: hi
}

// transpose + split: W[1024][N] fp32 -> dst[N][3072] = [hi | hi | lo]
template<int N>
__global__ __launch_bounds__(256) void prep_wsplit_kernel(
    const float* __restrict__ W, unsigned short* __restrict__ dst)
{
    __shared__ float tile[32][33];
    int n0 = blockIdx.x * 32, k0 = blockIdx.y * 32;
    int tx = threadIdx.x, ty = threadIdx.y;   // (32, 8)
    #pragma unroll
    for (int i = 0; i < 32; i += 8)
        tile[ty + i][tx] = W[(size_t)(k0 + ty + i) * N + n0 + tx];
    __syncthreads();
    #pragma unroll
    for (int i = 0; i < 32; i += 8) {
        int n = n0 + ty + i;
        int k = k0 + tx;
        float v = tile[tx][ty + i];
        __nv_bfloat16 hb = __float2bfloat16(v);
        __nv_bfloat16 lb = __float2bfloat16(v - __bfloat162float(hb));
        unsigned short hu = __bfloat16_as_ushort(hb);
        unsigned short lu = __bfloat16_as_ushort(lb);
        unsigned short* rp = dst + (size_t)n * K3_ + k;
        rp[0]    = hu;    // seg0: hi
        rp[1024] = hu;    // seg1: hi  (pairs with A's lo)
        rp[2048] = lu;    // seg2: lo  (pairs with A's hi)
    }
}

// ---------------------- mma.sync bf16 GEMM (tensor core) ---------------------
// D[128,128] = A[128x3072] . B[128x3072]^T, both K-major bf16, fp32 accum.
// 256 threads = 8 warps, warp tile 64x32, m16n8k16, cp.async double buffer.
// MODE 0: +bias, scatter into head-major g_Q/g_K/g_V. MODE 1: +bias -> Cout.
#define TSTRIDE 80                      // bytes per 32-col bf16 row (40 bf16, padded)
#define TILEB   (128 * TSTRIDE)         // 10240 B per operand tile
#define BUFB    (2 * TILEB)             // A+B per buffer
#define ROWB    (K3_ * 2)               // 6144 bytes per operand row
#define NCHUNK  (K3_ / 32)              // 96 chunks of 32 k

template<int MODE>
__global__ __launch_bounds__(256) void gemm_mma_kernel(
    const unsigned short* __restrict__ A, const unsigned short* __restrict__ Bm,
    const float* __restrict__ bias, float* __restrict__ Cout)
{
    __shared__ __align__(128) char smem[2 * BUFB];   // 40960 B
    const uint32_t sb = s2u(smem);

    const int tid = threadIdx.x, wid = tid >> 5, lid = tid & 31;
    const int bm = blockIdx.y * 128, bn = blockIdx.x * 128;
    const int wm = (wid & 1) * 64, wn = (wid >> 1) * 32;

    // ldmatrix lane address components
    const int g = lid >> 3, r = lid & 7;
    const uint32_t aoff = (uint32_t)(((g & 1) * 8 + r) * TSTRIDE + (g >> 1) * 16);
    const uint32_t boff = (uint32_t)(((g >> 1) * 8 + r) * TSTRIDE + (g & 1) * 16);

    // cp.async pattern: thread -> 2 chunks of A and B each (4x16B per 64B row-chunk)
    const int crow0 = tid >> 2, cc = tid & 3;        // +64 rows for the second
    const char* gAr = (const char*)A  + (size_t)bm * ROWB + (size_t)crow0 * ROWB + cc * 16;
    const char* gBr = (const char*)Bm + (size_t)bn * ROWB + (size_t)crow0 * ROWB + cc * 16;
    const uint32_t sOffA = (uint32_t)(crow0 * TSTRIDE + cc * 16);

    #define LOADCHUNK(kc, buf) do {                                            \
        uint32_t b0 = sb + (buf) * BUFB;                                       \
        _Pragma("unroll")                                                      \
        for (int i_ = 0; i_ < 2; i_++) {                                       \
            cp16(b0 + sOffA + i_ * (64 * TSTRIDE),                             \
                 gAr + (size_t)(kc) * 64 + (size_t)i_ * 64 * ROWB);            \
            cp16(b0 + TILEB + sOffA + i_ * (64 * TSTRIDE),                     \
                 gBr + (size_t)(kc) * 64 + (size_t)i_ * 64 * ROWB);            \
        }                                                                      \
        asm volatile("cp.async.commit_group;" ::: "memory");                   \
    } while (0)

    float acc[4][4][4];
    #pragma unroll
    for (int mt = 0; mt < 4; mt++)
        #pragma unroll
        for (int nt = 0; nt < 4; nt++)
            #pragma unroll
            for (int i = 0; i < 4; i++) acc[mt][nt][i] = 0.f;

    LOADCHUNK(0, 0);

    for (int c = 0; c < NCHUNK; c++) {
        if (c + 1 < NCHUNK) {
            LOADCHUNK(c + 1, (c + 1) & 1);
            asm volatile("cp.async.wait_group 1;" ::: "memory");
        } else {
            asm volatile("cp.async.wait_group 0;" ::: "memory");
        }
        __syncthreads();

        const uint32_t sAb = sb + (c & 1) * BUFB;
        const uint32_t sBb = sAb + TILEB;
        #pragma unroll
        for (int ks = 0; ks < 2; ks++) {
            uint32_t a[4][4];
            #pragma unroll
            for (int mt = 0; mt < 4; mt++)
                ldsm4(a[mt][0], a[mt][1], a[mt][2], a[mt][3],
                      sAb + (uint32_t)((wm + mt * 16) * TSTRIDE + ks * 32) + aoff);
            uint32_t b[4][2];
            #pragma unroll
            for (int nh = 0; nh < 2; nh++) {
                uint32_t r0, r1, r2, r3;
                ldsm4(r0, r1, r2, r3,
                      sBb + (uint32_t)((wn + nh * 16) * TSTRIDE + ks * 32) + boff);
                b[nh*2+0][0] = r0; b[nh*2+0][1] = r1;
                b[nh*2+1][0] = r2; b[nh*2+1][1] = r3;
            }
            #pragma unroll
            for (int mt = 0; mt < 4; mt++)
                #pragma unroll
                for (int nt = 0; nt < 4; nt++)
                    mma16816(acc[mt][nt], a[mt], b[nt]);
        }
        __syncthreads();
    }

    // ------------------------------- epilogue --------------------------------
    const int mrow = bm + wm + (lid >> 2);
    const int ncol = bn + wn + (lid & 3) * 2;
    #pragma unroll
    for (int mt = 0; mt < 4; mt++) {
        #pragma unroll
        for (int half = 0; half < 2; half++) {
            int m = mrow + mt * 16 + half * 8;
            #pragma unroll
            for (int nt = 0; nt < 4; nt++) {
                int col = ncol + nt * 8;
                float2 v;
                v.x = acc[mt][nt][half * 2 + 0] + bias[col];
                v.y = acc[mt][nt][half * 2 + 1] + bias[col + 1];
                if (MODE == 0) {
                    int which = col >> 10;
                    int ccv = col & 1023;
                    int h = ccv >> 6, d = ccv & 63;
                    float* dst = (which == 0) ? g_Q : (which == 1) ? g_K : g_V;
                    int bb = m >> 11, t = m & 2047;
                    *(float2*)&dst[(((size_t)(bb * H_ + h) * T_ + t) * D_ + d)] = v;
                } else {
                    *(float2*)&Cout[(size_t)m * 1024 + col] = v;
                }
            }
        }
    }
    #undef LOADCHUNK
}

// --------------------------- flash attention (fp32) --------------------------
__global__ __launch_bounds__(128) void flash_kernel()
{
    __shared__ __align__(16) float smem[128 * 68];

    const int tid = threadIdx.x;
    const int qt = blockIdx.x, h = blockIdx.y, b = blockIdx.z;
    const int qbase = qt * 128;
    const int qi = qbase + tid;
    const float scale = 0.125f;

    const float* Qg  = g_Q + ((size_t)(b*H_ + h)*T_ + qbase) * D_;
    const float* Kg0 = g_K + ((size_t)(b*H_ + h)*T_) * D_;
    const float* Vg0 = g_V + ((size_t)(b*H_ + h)*T_) * D_;

    float* Qs = smem;
    #pragma unroll
    for (int i = 0; i < 16; i++) {
        int idx4 = tid + i*128;
        int rr = idx4 >> 4, d4 = (idx4 & 15) * 4;
        float4 v = *(const float4*)&Qg[rr*64 + d4];
        *(float4*)&Qs[rr*68 + d4] = v;
    }
    __syncthreads();
    float q[64];
    #pragma unroll
    for (int d = 0; d < 64; d++) q[d] = Qs[tid*68 + d];
    __syncthreads();

    float* Kst = smem;              // [64][36]
    float* Vs  = smem + 64*36;      // [32][64]

    float mrow = -1e30f, lrow = 0.f;
    ull o2[32];
    #pragma unroll
    for (int i = 0; i < 32; i++) o2[i] = 0ull;

    const int kend = qbase + 128;
    for (int kb = 0; kb < kend; kb += 32) {
        #pragma unroll
        for (int i = 0; i < 4; i++) {
            int idx4 = tid + i*128;
            int j = idx4 >> 4, d4 = (idx4 & 15) * 4;
            float4 kv = *(const float4*)&Kg0[(size_t)(kb + j)*64 + d4];
            Kst[(d4+0)*36 + j] = kv.x;
            Kst[(d4+1)*36 + j] = kv.y;
            Kst[(d4+2)*36 + j] = kv.z;
            Kst[(d4+3)*36 + j] = kv.w;
            float4 vv = *(const float4*)&Vg0[(size_t)(kb + j)*64 + d4];
            *(float4*)&Vs[j*64 + d4] = vv;
        }
        __syncthreads();

        ull s2[16];
        #pragma unroll
        for (int jj = 0; jj < 16; jj++) s2[jj] = 0ull;
        #pragma unroll
        for (int d = 0; d < 64; d++) {
            ull qd = pack2(q[d], q[d]);
            const double2* kp = (const double2*)&Kst[d*36];
            #pragma unroll
            for (int j4 = 0; j4 < 8; j4++) {
                double2 kk = kp[j4];
                ffma2(s2[2*j4 + 0], qd, d2u(kk.x));
                ffma2(s2[2*j4 + 1], qd, d2u(kk.y));
            }
        }

        float sv[32];
        #pragma unroll
        for (int jj = 0; jj < 16; jj++) {
            float2 p = unpack2(s2[jj]);
            sv[2*jj]     = p.x * scale;
            sv[2*jj + 1] = p.y * scale;
        }
        if (kb + 31 > qi) {
            #pragma unroll
            for (int j = 0; j < 32; j++)
                if (kb + j > qi) sv[j] = -1e30f;
        }

        float mt = mrow;
        #pragma unroll
        for (int j = 0; j < 32; j++) mt = fmaxf(mt, sv[j]);
        float alpha = __expf(mrow - mt);
        mrow = mt;
        lrow *= alpha;
        ull al = pack2(alpha, alpha);
        #pragma unroll
        for (int i = 0; i < 32; i++) fmul2(o2[i], o2[i], al);

        #pragma unroll
        for (int j = 0; j < 32; j++) {
            float p = (sv[j] > -1e29f) ? __expf(sv[j] - mrow) : 0.f;
            lrow += p;
            ull pd = pack2(p, p);
            const double2* vp = (const double2*)&Vs[j*64];
            #pragma unroll
            for (int d4 = 0; d4 < 16; d4++) {
                double2 vv = vp[d4];
                ffma2(o2[2*d4 + 0], pd, d2u(vv.x));
                ffma2(o2[2*d4 + 1], pd, d2u(vv.y));
            }
        }
        __syncthreads();
    }

    float inv = 1.f / lrow;
    float* Op = g_O + ((size_t)(b*T_ + qi)) * C_ + h*64;
    #pragma unroll
    for (int dd = 0; dd < 16; dd++) {
        float2 a = unpack2(o2[2*dd]);
        float2 c = unpack2(o2[2*dd + 1]);
        float4 v;
        v.x = a.x * inv; v.y = a.y * inv; v.z = c.x * inv; v.w = c.y * inv;
        *(float4*)&Op[dd*4] = v;
    }
}

// ------------------------------- launcher -----------------------------------
extern "C" void kernel_launch(void* const* d_in, const int* in_sizes, int n_in,
                              void* d_out, int out_size) {
    const float* x    = (const float*)d_in[0];   // [4,2048,1024]
    const float* Wqkv = (const float*)d_in[1];   // [1024,3072]
    const float* bqkv = (const float*)d_in[2];   // [3072]
    const float* Wout = (const float*)d_in[3];   // [1024,1024]
    const float* bout = (const float*)d_in[4];   // [1024]
    float* out = (float*)d_out;                  // [4,2048,1024]

    unsigned short* gA  = nullptr; cudaGetSymbolAddress((void**)&gA,  g_A);
    unsigned short* gBq = nullptr; cudaGetSymbolAddress((void**)&gBq, g_Bq);
    unsigned short* gBo = nullptr; cudaGetSymbolAddress((void**)&gBo, g_Bo);
    float* gO = nullptr; cudaGetSymbolAddress((void**)&gO, g_O);

    // 1) split/transpose prep
    prep_split_kernel<<<8192, 256>>>(x, gA);
    prep_wsplit_kernel<3072><<<dim3(96, 32), dim3(32, 8)>>>(Wqkv, gBq);
    prep_wsplit_kernel<1024><<<dim3(32, 32), dim3(32, 8)>>>(Wout, gBo);

    // 2) QKV projection (tensor core mma.sync) -> head-major g_Q/g_K/g_V
    gemm_mma_kernel<0><<<dim3(24, 64), 256>>>(gA, gBq, bqkv, nullptr);

    // 3) causal flash attention -> g_O [B,T,C]
    flash_kernel<<<dim3(16, 16, 4), 128>>>();

    // 4) split g_O, output projection (tensor core mma.sync) -> d_out
    prep_split_kernel<<<8192, 256>>>(gO, gA);
    gemm_mma_kernel<1><<<dim3(8, 64), 256>>>(gA, gBo, bout, out);
}

// round 8
// speedup vs baseline: 2.3264x; 1.8862x over previous
#include <cuda_runtime.h>
#include <cuda_bf16.h>
#include <cstdint>

#define B_   4
#define T_   2048
#define C_   1024
#define H_   16
#define D_   64
#define BT_  (B_*T_)
#define BH_  (B_*H_)
#define K3_  3072     // 3-segment split K for projections

// ------------------------- scratch (device globals) -------------------------
__device__ __align__(16) float g_O[BT_*C_];                  // [B][T][C]
__device__ __align__(16) unsigned short g_A [BT_*K3_];       // x-split / O-split
__device__ __align__(16) unsigned short g_Bq[3*C_*K3_];      // Wqkv^T split
__device__ __align__(16) unsigned short g_Bo[C_*K3_];        // Wout^T split
__device__ __align__(16) unsigned short g_Qs[BH_*T_*128];    // [bh][t][hi64|lo64], Q pre-scaled
__device__ __align__(16) unsigned short g_Ks[BH_*T_*128];    // [bh][t][hi64|lo64]
__device__ __align__(16) unsigned short g_Vt[BH_*128*T_];    // [bh][hi d0..63, lo d0..63][t]

// ------------------------------ small helpers -------------------------------
__device__ __forceinline__ uint32_t s2u(const void* p) {
    uint32_t a;
    asm("{ .reg .u64 t; cvta.to.shared.u64 t, %1; cvt.u32.u64 %0, t; }" : "=r"(a) : "l"(p));
    return a;
}
__device__ __forceinline__ void cp16(uint32_t d, const void* s) {
    asm volatile("cp.async.cg.shared.global [%0], [%1], 16;" :: "r"(d), "l"(s));
}
__device__ __forceinline__ void ldsm4(uint32_t& r0, uint32_t& r1, uint32_t& r2, uint32_t& r3,
                                      uint32_t a) {
    asm volatile("ldmatrix.sync.aligned.m8n8.x4.shared.b16 {%0,%1,%2,%3}, [%4];"
                 : "=r"(r0), "=r"(r1), "=r"(r2), "=r"(r3) : "r"(a));
}
__device__ __forceinline__ void mma16816(float* c, const uint32_t* a, const uint32_t* b) {
    asm volatile("mma.sync.aligned.m16n8k16.row.col.f32.bf16.bf16.f32 "
                 "{%0,%1,%2,%3}, {%4,%5,%6,%7}, {%8,%9}, {%0,%1,%2,%3};"
                 : "+f"(c[0]), "+f"(c[1]), "+f"(c[2]), "+f"(c[3])
                 : "r"(a[0]), "r"(a[1]), "r"(a[2]), "r"(a[3]), "r"(b[0]), "r"(b[1]));
}
// pack two floats into bf16x2: low half = first arg
__device__ __forceinline__ uint32_t pk_bf2(float lo, float hi) {
    uint32_t d;
    asm("cvt.rn.bf16x2.f32 %0, %1, %2;" : "=r"(d) : "f"(hi), "f"(lo));
    return d;
}
__device__ __forceinline__ float bf2_lo(uint32_t u) { return __uint_as_float(u << 16); }
__device__ __forceinline__ float bf2_hi(uint32_t u) { return __uint_as_float(u & 0xffff0000u); }

// ------------------------------ prep kernels --------------------------------
// split fp32 [rows][1024] -> bf16 [rows][3072] = [hi | lo | hi]
__global__ __launch_bounds__(256) void prep_split_kernel(
    const float* __restrict__ src, unsigned short* __restrict__ dst)
{
    int idx = blockIdx.x * 256 + threadIdx.x;
    int row = idx >> 8;
    int c4  = idx & 255;
    float4 v = *(const float4*)(src + (size_t)row * 1024 + c4 * 4);
    float f[4] = {v.x, v.y, v.z, v.w};
    unsigned short h[4], l[4];
    #pragma unroll
    for (int i = 0; i < 4; i++) {
        __nv_bfloat16 hb = __float2bfloat16(f[i]);
        __nv_bfloat16 lb = __float2bfloat16(f[i] - __bfloat162float(hb));
        h[i] = __bfloat16_as_ushort(hb);
        l[i] = __bfloat16_as_ushort(lb);
    }
    uint64_t hp = (uint64_t)h[0] | ((uint64_t)h[1] << 16) | ((uint64_t)h[2] << 32) | ((uint64_t)h[3] << 48);
    uint64_t lp = (uint64_t)l[0] | ((uint64_t)l[1] << 16) | ((uint64_t)l[2] << 32) | ((uint64_t)l[3] << 48);
    unsigned short* rp = dst + (size_t)row * K3_ + c4 * 4;
    *(uint64_t*)(rp)        = hp;
    *(uint64_t*)(rp + 1024) = lp;
    *(uint64_t*)(rp + 2048) = hp;
}

// transpose + split: W[1024][N] fp32 -> dst[N][3072] = [hi | hi | lo]
template<int N>
__global__ __launch_bounds__(256) void prep_wsplit_kernel(
    const float* __restrict__ W, unsigned short* __restrict__ dst)
{
    __shared__ float tile[32][33];
    int n0 = blockIdx.x * 32, k0 = blockIdx.y * 32;
    int tx = threadIdx.x, ty = threadIdx.y;
    #pragma unroll
    for (int i = 0; i < 32; i += 8)
        tile[ty + i][tx] = W[(size_t)(k0 + ty + i) * N + n0 + tx];
    __syncthreads();
    #pragma unroll
    for (int i = 0; i < 32; i += 8) {
        int n = n0 + ty + i;
        int k = k0 + tx;
        float v = tile[tx][ty + i];
        __nv_bfloat16 hb = __float2bfloat16(v);
        __nv_bfloat16 lb = __float2bfloat16(v - __bfloat162float(hb));
        unsigned short hu = __bfloat16_as_ushort(hb);
        unsigned short lu = __bfloat16_as_ushort(lb);
        unsigned short* rp = dst + (size_t)n * K3_ + k;
        rp[0]    = hu;
        rp[1024] = hu;
        rp[2048] = lu;
    }
}

// ---------------------- mma.sync bf16 GEMM (tensor core) ---------------------
#define TSTRIDE 80
#define TILEB   (128 * TSTRIDE)
#define BUFB    (2 * TILEB)
#define ROWB    (K3_ * 2)
#define NCHUNK  (K3_ / 32)

template<int MODE>
__global__ __launch_bounds__(256) void gemm_mma_kernel(
    const unsigned short* __restrict__ A, const unsigned short* __restrict__ Bm,
    const float* __restrict__ bias, float* __restrict__ Cout)
{
    __shared__ __align__(128) char smem[2 * BUFB];
    const uint32_t sb = s2u(smem);

    const int tid = threadIdx.x, wid = tid >> 5, lid = tid & 31;
    const int bm = blockIdx.y * 128, bn = blockIdx.x * 128;
    const int wm = (wid & 1) * 64, wn = (wid >> 1) * 32;

    const int g = lid >> 3, r = lid & 7;
    const uint32_t aoff = (uint32_t)(((g & 1) * 8 + r) * TSTRIDE + (g >> 1) * 16);
    const uint32_t boff = (uint32_t)(((g >> 1) * 8 + r) * TSTRIDE + (g & 1) * 16);

    const int crow0 = tid >> 2, cc = tid & 3;
    const char* gAr = (const char*)A  + (size_t)bm * ROWB + (size_t)crow0 * ROWB + cc * 16;
    const char* gBr = (const char*)Bm + (size_t)bn * ROWB + (size_t)crow0 * ROWB + cc * 16;
    const uint32_t sOffA = (uint32_t)(crow0 * TSTRIDE + cc * 16);

    #define LOADCHUNK(kc, buf) do {                                            \
        uint32_t b0 = sb + (buf) * BUFB;                                       \
        _Pragma("unroll")                                                      \
        for (int i_ = 0; i_ < 2; i_++) {                                       \
            cp16(b0 + sOffA + i_ * (64 * TSTRIDE),                             \
                 gAr + (size_t)(kc) * 64 + (size_t)i_ * 64 * ROWB);            \
            cp16(b0 + TILEB + sOffA + i_ * (64 * TSTRIDE),                     \
                 gBr + (size_t)(kc) * 64 + (size_t)i_ * 64 * ROWB);            \
        }                                                                      \
        asm volatile("cp.async.commit_group;" ::: "memory");                   \
    } while (0)

    float acc[4][4][4];
    #pragma unroll
    for (int mt = 0; mt < 4; mt++)
        #pragma unroll
        for (int nt = 0; nt < 4; nt++)
            #pragma unroll
            for (int i = 0; i < 4; i++) acc[mt][nt][i] = 0.f;

    LOADCHUNK(0, 0);

    for (int c = 0; c < NCHUNK; c++) {
        if (c + 1 < NCHUNK) {
            LOADCHUNK(c + 1, (c + 1) & 1);
            asm volatile("cp.async.wait_group 1;" ::: "memory");
        } else {
            asm volatile("cp.async.wait_group 0;" ::: "memory");
        }
        __syncthreads();

        const uint32_t sAb = sb + (c & 1) * BUFB;
        const uint32_t sBb = sAb + TILEB;
        #pragma unroll
        for (int ks = 0; ks < 2; ks++) {
            uint32_t a[4][4];
            #pragma unroll
            for (int mt = 0; mt < 4; mt++)
                ldsm4(a[mt][0], a[mt][1], a[mt][2], a[mt][3],
                      sAb + (uint32_t)((wm + mt * 16) * TSTRIDE + ks * 32) + aoff);
            uint32_t b[4][2];
            #pragma unroll
            for (int nh = 0; nh < 2; nh++) {
                uint32_t r0, r1, r2, r3;
                ldsm4(r0, r1, r2, r3,
                      sBb + (uint32_t)((wn + nh * 16) * TSTRIDE + ks * 32) + boff);
                b[nh*2+0][0] = r0; b[nh*2+0][1] = r1;
                b[nh*2+1][0] = r2; b[nh*2+1][1] = r3;
            }
            #pragma unroll
            for (int mt = 0; mt < 4; mt++)
                #pragma unroll
                for (int nt = 0; nt < 4; nt++)
                    mma16816(acc[mt][nt], a[mt], b[nt]);
        }
        __syncthreads();
    }

    // ------------------------------- epilogue --------------------------------
    const int mrow = bm + wm + (lid >> 2);
    const int ncol = bn + wn + (lid & 3) * 2;
    #pragma unroll
    for (int mt = 0; mt < 4; mt++) {
        #pragma unroll
        for (int half = 0; half < 2; half++) {
            int m = mrow + mt * 16 + half * 8;
            #pragma unroll
            for (int nt = 0; nt < 4; nt++) {
                int col = ncol + nt * 8;
                float vx = acc[mt][nt][half * 2 + 0] + bias[col];
                float vy = acc[mt][nt][half * 2 + 1] + bias[col + 1];
                if (MODE == 0) {
                    const int which = bn >> 10;          // uniform per block
                    int ccv = col & 1023;
                    int hh = ccv >> 6, d = ccv & 63;
                    int bb = m >> 11, t = m & 2047;
                    int bh = bb * H_ + hh;
                    if (which == 0) {                    // Q: pre-scale by 1/sqrt(64)
                        vx *= 0.125f; vy *= 0.125f;
                        uint32_t hi2 = pk_bf2(vx, vy);
                        uint32_t lo2 = pk_bf2(vx - bf2_lo(hi2), vy - bf2_hi(hi2));
                        size_t idx = ((size_t)bh * T_ + t) * 128 + d;
                        *(uint32_t*)&g_Qs[idx]      = hi2;
                        *(uint32_t*)&g_Qs[idx + 64] = lo2;
                    } else if (which == 1) {             // K
                        uint32_t hi2 = pk_bf2(vx, vy);
                        uint32_t lo2 = pk_bf2(vx - bf2_lo(hi2), vy - bf2_hi(hi2));
                        size_t idx = ((size_t)bh * T_ + t) * 128 + d;
                        *(uint32_t*)&g_Ks[idx]      = hi2;
                        *(uint32_t*)&g_Ks[idx + 64] = lo2;
                    } else {                             // V -> transposed split
                        uint32_t hi2 = pk_bf2(vx, vy);
                        uint32_t lo2 = pk_bf2(vx - bf2_lo(hi2), vy - bf2_hi(hi2));
                        size_t rb = (size_t)bh * 128;
                        g_Vt[(rb + d         ) * T_ + t] = (unsigned short)(hi2 & 0xffff);
                        g_Vt[(rb + d + 1     ) * T_ + t] = (unsigned short)(hi2 >> 16);
                        g_Vt[(rb + 64 + d    ) * T_ + t] = (unsigned short)(lo2 & 0xffff);
                        g_Vt[(rb + 64 + d + 1) * T_ + t] = (unsigned short)(lo2 >> 16);
                    }
                } else {
                    float2 v; v.x = vx; v.y = vy;
                    *(float2*)&Cout[(size_t)m * 1024 + col] = v;
                }
            }
        }
    }
    #undef LOADCHUNK
}

// ------------------- flash attention (tensor core, bf16 split) ---------------
#define QSTR    272                      // smem row stride bytes (136 bf16)
#define FK_TILE (64 * QSTR)              // 17408
#define FLASH_SMEM (128 * QSTR + 4 * FK_TILE)   // 104448

__global__ __launch_bounds__(128) void flash_mma_kernel()
{
    extern __shared__ char fsm[];
    const uint32_t sQ  = s2u(fsm);
    const uint32_t sK0 = sQ + 128 * QSTR;
    const uint32_t sV0 = sK0 + 2 * FK_TILE;

    const int tid = threadIdx.x, wid = tid >> 5, lid = tid & 31;
    const int qb = blockIdx.x * 128, h = blockIdx.y, b = blockIdx.z;
    const int bh = b * H_ + h;
    const int qwb = qb + wid * 32;

    const char* Qg = (const char*)(g_Qs + ((size_t)bh * T_ + qb) * 128);
    const char* Kg = (const char*)(g_Ks + ((size_t)bh * T_) * 128);
    const char* Vg = (const char*)(g_Vt + (size_t)bh * 128 * T_);

    // Q tile (128 rows x 256B) -> smem
    #pragma unroll
    for (int i = 0; i < 16; i++) {
        int idx = tid + i * 128, row = idx >> 4, c16 = idx & 15;
        cp16(sQ + row * QSTR + c16 * 16, Qg + row * 256 + c16 * 16);
    }
    asm volatile("cp.async.commit_group;" ::: "memory");

    #define LOADKV(kb_, buf_) do {                                               \
        uint32_t sk = sK0 + (buf_) * FK_TILE, sv = sV0 + (buf_) * FK_TILE;       \
        _Pragma("unroll")                                                        \
        for (int i_ = 0; i_ < 8; i_++) {                                         \
            int idx = tid + i_ * 128, row = idx >> 4, c16 = idx & 15;            \
            cp16(sk + row * QSTR + c16 * 16,                                     \
                 Kg + (size_t)((kb_) + row) * 256 + c16 * 16);                   \
            int seg = c16 >> 3, kc = c16 & 7;                                    \
            cp16(sv + row * QSTR + c16 * 16,                                     \
                 Vg + (size_t)(seg * 64 + row) * 4096 + (size_t)(kb_) * 2 + kc * 16); \
        }                                                                        \
        asm volatile("cp.async.commit_group;" ::: "memory");                     \
    } while (0)

    LOADKV(0, 0);

    const int g = lid >> 3, r = lid & 7;
    const uint32_t aoff  = (uint32_t)(((g & 1) * 8 + r) * QSTR + (g >> 1) * 16);
    const uint32_t boff  = (uint32_t)(((g >> 1) * 8 + r) * QSTR + (g & 1) * 16);
    const uint32_t qwoff = (uint32_t)(wid * 32) * QSTR;

    float O[2][8][4];
    #pragma unroll
    for (int mt = 0; mt < 2; mt++)
        #pragma unroll
        for (int nt = 0; nt < 8; nt++)
            #pragma unroll
            for (int i = 0; i < 4; i++) O[mt][nt][i] = 0.f;
    float mrow[2][2] = {{-1e30f, -1e30f}, {-1e30f, -1e30f}};
    float lrow[2][2] = {{0.f, 0.f}, {0.f, 0.f}};

    const int ntiles = (qb + 128) >> 6;

    for (int t = 0; t < ntiles; t++) {
        const int kb = t << 6;
        if (t + 1 < ntiles) {
            LOADKV((t + 1) << 6, (t + 1) & 1);
            asm volatile("cp.async.wait_group 1;" ::: "memory");
        } else {
            asm volatile("cp.async.wait_group 0;" ::: "memory");
        }
        __syncthreads();

        if (kb <= qwb + 31) {
            const uint32_t sK = sK0 + (t & 1) * FK_TILE;
            const uint32_t sV = sV0 + (t & 1) * FK_TILE;

            // ---- S = Q . K^T (3-term split) ----
            float S[2][8][4];
            #pragma unroll
            for (int mt = 0; mt < 2; mt++)
                #pragma unroll
                for (int nt = 0; nt < 8; nt++)
                    #pragma unroll
                    for (int i = 0; i < 4; i++) S[mt][nt][i] = 0.f;

            #pragma unroll
            for (int pass = 0; pass < 3; pass++) {
                const uint32_t aseg = (pass == 1) ? 128u : 0u;   // Q lo segment
                const uint32_t bseg = (pass == 2) ? 128u : 0u;   // K lo segment
                #pragma unroll
                for (int kt = 0; kt < 4; kt++) {
                    uint32_t a0[4], a1[4];
                    ldsm4(a0[0], a0[1], a0[2], a0[3],
                          sQ + qwoff + aseg + kt * 32 + aoff);
                    ldsm4(a1[0], a1[1], a1[2], a1[3],
                          sQ + qwoff + 16 * QSTR + aseg + kt * 32 + aoff);
                    #pragma unroll
                    for (int np = 0; np < 4; np++) {
                        uint32_t b0, b1, b2, b3;
                        ldsm4(b0, b1, b2, b3,
                              sK + (uint32_t)(np * 16) * QSTR + bseg + kt * 32 + boff);
                        uint32_t bb0[2] = {b0, b1}, bb1[2] = {b2, b3};
                        mma16816(S[0][np * 2 + 0], a0, bb0);
                        mma16816(S[0][np * 2 + 1], a0, bb1);
                        mma16816(S[1][np * 2 + 0], a1, bb0);
                        mma16816(S[1][np * 2 + 1], a1, bb1);
                    }
                }
            }

            // ---- causal mask ----
            if (kb + 63 > qwb) {
                #pragma unroll
                for (int mt = 0; mt < 2; mt++) {
                    int q0 = qwb + mt * 16 + (lid >> 2);
                    #pragma unroll
                    for (int nt = 0; nt < 8; nt++) {
                        int key = kb + nt * 8 + (lid & 3) * 2;
                        if (key     > q0)     S[mt][nt][0] = -1e30f;
                        if (key + 1 > q0)     S[mt][nt][1] = -1e30f;
                        if (key     > q0 + 8) S[mt][nt][2] = -1e30f;
                        if (key + 1 > q0 + 8) S[mt][nt][3] = -1e30f;
                    }
                }
            }

            // ---- online softmax + P split ----
            uint32_t phi[2][4][4], plo[2][4][4];
            #pragma unroll
            for (int mt = 0; mt < 2; mt++) {
                float mn0 = -1e30f, mn1 = -1e30f;
                #pragma unroll
                for (int nt = 0; nt < 8; nt++) {
                    mn0 = fmaxf(mn0, fmaxf(S[mt][nt][0], S[mt][nt][1]));
                    mn1 = fmaxf(mn1, fmaxf(S[mt][nt][2], S[mt][nt][3]));
                }
                mn0 = fmaxf(mn0, __shfl_xor_sync(0xffffffffu, mn0, 1));
                mn0 = fmaxf(mn0, __shfl_xor_sync(0xffffffffu, mn0, 2));
                mn1 = fmaxf(mn1, __shfl_xor_sync(0xffffffffu, mn1, 1));
                mn1 = fmaxf(mn1, __shfl_xor_sync(0xffffffffu, mn1, 2));
                float mx0 = fmaxf(mrow[mt][0], mn0), mx1 = fmaxf(mrow[mt][1], mn1);
                float al0 = __expf(mrow[mt][0] - mx0), al1 = __expf(mrow[mt][1] - mx1);
                mrow[mt][0] = mx0; mrow[mt][1] = mx1;
                float s0 = 0.f, s1 = 0.f;
                #pragma unroll
                for (int nt = 0; nt < 8; nt++) {
                    float p0 = __expf(S[mt][nt][0] - mx0);
                    float p1 = __expf(S[mt][nt][1] - mx0);
                    float p2 = __expf(S[mt][nt][2] - mx1);
                    float p3 = __expf(S[mt][nt][3] - mx1);
                    s0 += p0 + p1; s1 += p2 + p3;
                    S[mt][nt][0] = p0; S[mt][nt][1] = p1;
                    S[mt][nt][2] = p2; S[mt][nt][3] = p3;
                }
                s0 += __shfl_xor_sync(0xffffffffu, s0, 1);
                s0 += __shfl_xor_sync(0xffffffffu, s0, 2);
                s1 += __shfl_xor_sync(0xffffffffu, s1, 1);
                s1 += __shfl_xor_sync(0xffffffffu, s1, 2);
                lrow[mt][0] = lrow[mt][0] * al0 + s0;
                lrow[mt][1] = lrow[mt][1] * al1 + s1;
                #pragma unroll
                for (int nt = 0; nt < 8; nt++) {
                    O[mt][nt][0] *= al0; O[mt][nt][1] *= al0;
                    O[mt][nt][2] *= al1; O[mt][nt][3] *= al1;
                }
                // pack P fragments: C-frag(ntiles 2kt,2kt+1) -> A-frag(k16 tile kt)
                #pragma unroll
                for (int kt = 0; kt < 4; kt++) {
                    uint32_t h0 = pk_bf2(S[mt][2*kt  ][0], S[mt][2*kt  ][1]);
                    uint32_t h1 = pk_bf2(S[mt][2*kt  ][2], S[mt][2*kt  ][3]);
                    uint32_t h2 = pk_bf2(S[mt][2*kt+1][0], S[mt][2*kt+1][1]);
                    uint32_t h3 = pk_bf2(S[mt][2*kt+1][2], S[mt][2*kt+1][3]);
                    phi[mt][kt][0] = h0; phi[mt][kt][1] = h1;
                    phi[mt][kt][2] = h2; phi[mt][kt][3] = h3;
                    plo[mt][kt][0] = pk_bf2(S[mt][2*kt  ][0] - bf2_lo(h0),
                                            S[mt][2*kt  ][1] - bf2_hi(h0));
                    plo[mt][kt][1] = pk_bf2(S[mt][2*kt  ][2] - bf2_lo(h1),
                                            S[mt][2*kt  ][3] - bf2_hi(h1));
                    plo[mt][kt][2] = pk_bf2(S[mt][2*kt+1][0] - bf2_lo(h2),
                                            S[mt][2*kt+1][1] - bf2_hi(h2));
                    plo[mt][kt][3] = pk_bf2(S[mt][2*kt+1][2] - bf2_lo(h3),
                                            S[mt][2*kt+1][3] - bf2_hi(h3));
                }
            }

            // ---- O += P . V (3-term split: Phi*Vhi + Plo*Vhi + Phi*Vlo) ----
            #pragma unroll
            for (int pass = 0; pass < 3; pass++) {
                const uint32_t bcol = (pass == 2) ? 128u : 0u;   // V lo columns
                #pragma unroll
                for (int kt = 0; kt < 4; kt++) {
                    const uint32_t* A0 = (pass == 1) ? plo[0][kt] : phi[0][kt];
                    const uint32_t* A1 = (pass == 1) ? plo[1][kt] : phi[1][kt];
                    #pragma unroll
                    for (int np = 0; np < 4; np++) {
                        uint32_t b0, b1, b2, b3;
                        ldsm4(b0, b1, b2, b3,
                              sV + (uint32_t)(np * 16) * QSTR + bcol + kt * 32 + boff);
                        uint32_t bb0[2] = {b0, b1}, bb1[2] = {b2, b3};
                        mma16816(O[0][np * 2 + 0], A0, bb0);
                        mma16816(O[0][np * 2 + 1], A0, bb1);
                        mma16816(O[1][np * 2 + 0], A1, bb0);
                        mma16816(O[1][np * 2 + 1], A1, bb1);
                    }
                }
            }
        }
        __syncthreads();
    }

    // ---- normalize + write ----
    #pragma unroll
    for (int mt = 0; mt < 2; mt++) {
        float inv0 = 1.f / lrow[mt][0], inv1 = 1.f / lrow[mt][1];
        int q0 = qwb + mt * 16 + (lid >> 2);
        float* o0 = g_O + ((size_t)b * T_ + q0) * C_ + h * 64 + (lid & 3) * 2;
        float* o1 = o0 + 8 * C_;
        #pragma unroll
        for (int nt = 0; nt < 8; nt++) {
            float2 v0, v1;
            v0.x = O[mt][nt][0] * inv0; v0.y = O[mt][nt][1] * inv0;
            v1.x = O[mt][nt][2] * inv1; v1.y = O[mt][nt][3] * inv1;
            *(float2*)(o0 + nt * 8) = v0;
            *(float2*)(o1 + nt * 8) = v1;
        }
    }
    #undef LOADKV
}

// ------------------------------- launcher -----------------------------------
extern "C" void kernel_launch(void* const* d_in, const int* in_sizes, int n_in,
                              void* d_out, int out_size) {
    const float* x    = (const float*)d_in[0];   // [4,2048,1024]
    const float* Wqkv = (const float*)d_in[1];   // [1024,3072]
    const float* bqkv = (const float*)d_in[2];   // [3072]
    const float* Wout = (const float*)d_in[3];   // [1024,1024]
    const float* bout = (const float*)d_in[4];   // [1024]
    float* out = (float*)d_out;                  // [4,2048,1024]

    cudaFuncSetAttribute(flash_mma_kernel,
                         cudaFuncAttributeMaxDynamicSharedMemorySize, FLASH_SMEM);

    unsigned short* gA  = nullptr; cudaGetSymbolAddress((void**)&gA,  g_A);
    unsigned short* gBq = nullptr; cudaGetSymbolAddress((void**)&gBq, g_Bq);
    unsigned short* gBo = nullptr; cudaGetSymbolAddress((void**)&gBo, g_Bo);
    float* gO = nullptr; cudaGetSymbolAddress((void**)&gO, g_O);

    // 1) split/transpose prep
    prep_split_kernel<<<8192, 256>>>(x, gA);
    prep_wsplit_kernel<3072><<<dim3(96, 32), dim3(32, 8)>>>(Wqkv, gBq);
    prep_wsplit_kernel<1024><<<dim3(32, 32), dim3(32, 8)>>>(Wout, gBo);

    // 2) QKV projection -> split bf16 Q/K/V^T (head-major)
    gemm_mma_kernel<0><<<dim3(24, 64), 256>>>(gA, gBq, bqkv, nullptr);

    // 3) causal flash attention (tensor cores) -> g_O [B,T,C]
    flash_mma_kernel<<<dim3(16, 16, 4), 128, FLASH_SMEM>>>();

    // 4) split g_O, output projection -> d_out
    prep_split_kernel<<<8192, 256>>>(gO, gA);
    gemm_mma_kernel<1><<<dim3(8, 64), 256>>>(gA, gBo, bout, out);
}

// round 9
// speedup vs baseline: 2.7227x; 1.1704x over previous
#include <cuda_runtime.h>
#include <cuda_bf16.h>
#include <cstdint>

#define B_   4
#define T_   2048
#define C_   1024
#define H_   16
#define D_   64
#define BT_  (B_*T_)
#define BH_  (B_*H_)
#define K3_  3072     // logical 3-segment K for projections
#define K2_  2048     // A stored as [hi|lo] only (seg2 == seg0)

// ------------------------- scratch (device globals) -------------------------
__device__ __align__(16) float g_O[BT_*C_];                  // [B][T][C]
__device__ __align__(16) unsigned short g_A [BT_*K2_];       // x-split / O-split [hi|lo]
__device__ __align__(16) unsigned short g_Bq[3*C_*K3_];      // Wqkv^T split [hi|hi|lo]
__device__ __align__(16) unsigned short g_Bo[C_*K3_];        // Wout^T split [hi|hi|lo]
__device__ __align__(16) unsigned short g_Qs[BH_*T_*128];    // [bh][t][hi64|lo64], Q pre-scaled
__device__ __align__(16) unsigned short g_Ks[BH_*T_*128];    // [bh][t][hi64|lo64]
__device__ __align__(16) unsigned short g_Vt[BH_*128*T_];    // [bh][hi d0..63, lo d0..63][t]

// ------------------------------ small helpers -------------------------------
__device__ __forceinline__ uint32_t s2u(const void* p) {
    uint32_t a;
    asm("{ .reg .u64 t; cvta.to.shared.u64 t, %1; cvt.u32.u64 %0, t; }" : "=r"(a) : "l"(p));
    return a;
}
__device__ __forceinline__ void cp16(uint32_t d, const void* s) {
    asm volatile("cp.async.cg.shared.global [%0], [%1], 16;" :: "r"(d), "l"(s));
}
__device__ __forceinline__ void ldsm4(uint32_t& r0, uint32_t& r1, uint32_t& r2, uint32_t& r3,
                                      uint32_t a) {
    asm volatile("ldmatrix.sync.aligned.m8n8.x4.shared.b16 {%0,%1,%2,%3}, [%4];"
                 : "=r"(r0), "=r"(r1), "=r"(r2), "=r"(r3) : "r"(a));
}
__device__ __forceinline__ void mma16816(float* c, const uint32_t* a, const uint32_t* b) {
    asm volatile("mma.sync.aligned.m16n8k16.row.col.f32.bf16.bf16.f32 "
                 "{%0,%1,%2,%3}, {%4,%5,%6,%7}, {%8,%9}, {%0,%1,%2,%3};"
                 : "+f"(c[0]), "+f"(c[1]), "+f"(c[2]), "+f"(c[3])
                 : "r"(a[0]), "r"(a[1]), "r"(a[2]), "r"(a[3]), "r"(b[0]), "r"(b[1]));
}
// pack two floats into bf16x2: low half = first arg
__device__ __forceinline__ uint32_t pk_bf2(float lo, float hi) {
    uint32_t d;
    asm("cvt.rn.bf16x2.f32 %0, %1, %2;" : "=r"(d) : "f"(hi), "f"(lo));
    return d;
}
__device__ __forceinline__ float bf2_lo(uint32_t u) { return __uint_as_float(u << 16); }
__device__ __forceinline__ float bf2_hi(uint32_t u) { return __uint_as_float(u & 0xffff0000u); }

// ------------------------------ prep kernels --------------------------------
// split fp32 [rows][1024] -> bf16 [rows][2048] = [hi | lo]
__global__ __launch_bounds__(256) void prep_split_kernel(
    const float* __restrict__ src, unsigned short* __restrict__ dst)
{
    int idx = blockIdx.x * 256 + threadIdx.x;
    int row = idx >> 8;
    int c4  = idx & 255;
    float4 v = *(const float4*)(src + (size_t)row * 1024 + c4 * 4);
    float f[4] = {v.x, v.y, v.z, v.w};
    unsigned short h[4], l[4];
    #pragma unroll
    for (int i = 0; i < 4; i++) {
        __nv_bfloat16 hb = __float2bfloat16(f[i]);
        __nv_bfloat16 lb = __float2bfloat16(f[i] - __bfloat162float(hb));
        h[i] = __bfloat16_as_ushort(hb);
        l[i] = __bfloat16_as_ushort(lb);
    }
    uint64_t hp = (uint64_t)h[0] | ((uint64_t)h[1] << 16) | ((uint64_t)h[2] << 32) | ((uint64_t)h[3] << 48);
    uint64_t lp = (uint64_t)l[0] | ((uint64_t)l[1] << 16) | ((uint64_t)l[2] << 32) | ((uint64_t)l[3] << 48);
    unsigned short* rp = dst + (size_t)row * K2_ + c4 * 4;
    *(uint64_t*)(rp)        = hp;
    *(uint64_t*)(rp + 1024) = lp;
}

// transpose + split: W[1024][N] fp32 -> dst[N][3072] = [hi | hi | lo]
template<int N>
__global__ __launch_bounds__(256) void prep_wsplit_kernel(
    const float* __restrict__ W, unsigned short* __restrict__ dst)
{
    __shared__ float tile[32][33];
    int n0 = blockIdx.x * 32, k0 = blockIdx.y * 32;
    int tx = threadIdx.x, ty = threadIdx.y;
    #pragma unroll
    for (int i = 0; i < 32; i += 8)
        tile[ty + i][tx] = W[(size_t)(k0 + ty + i) * N + n0 + tx];
    __syncthreads();
    #pragma unroll
    for (int i = 0; i < 32; i += 8) {
        int n = n0 + ty + i;
        int k = k0 + tx;
        float v = tile[tx][ty + i];
        __nv_bfloat16 hb = __float2bfloat16(v);
        __nv_bfloat16 lb = __float2bfloat16(v - __bfloat162float(hb));
        unsigned short hu = __bfloat16_as_ushort(hb);
        unsigned short lu = __bfloat16_as_ushort(lb);
        unsigned short* rp = dst + (size_t)n * K3_ + k;
        rp[0]    = hu;
        rp[1024] = hu;
        rp[2048] = lu;
    }
}

// ---------------------- mma.sync bf16 GEMM (tensor core) ---------------------
// D[128,128] = A[128, K2 as 3-seg] . B[128, K3]^T, K-chunk 64, 2-stage, 1 sync/chunk.
#define KCH   64
#define TSTR2 144                        // bytes per 64-k row (128 B + 16 pad)
#define TILE2 (128 * TSTR2)              // 18432
#define STG2  (2 * TILE2)                // A+B per stage = 36864
#define GSMEM (2 * STG2)                 // 73728
#define NCHU  (K3_ / KCH)                // 48
#define ROWA  (K2_ * 2)                  // 4096 B
#define ROWB  (K3_ * 2)                  // 6144 B

template<int MODE>
__global__ __launch_bounds__(256) void gemm_mma_kernel(
    const unsigned short* __restrict__ A, const unsigned short* __restrict__ Bm,
    const float* __restrict__ bias, float* __restrict__ Cout)
{
    extern __shared__ __align__(128) char smem[];
    const uint32_t sb = s2u(smem);

    const int tid = threadIdx.x, wid = tid >> 5, lid = tid & 31;
    const int bm = blockIdx.y * 128, bn = blockIdx.x * 128;
    const int wm = (wid & 1) * 64, wn = (wid >> 1) * 32;

    const int g = lid >> 3, r = lid & 7;
    const uint32_t aoff = (uint32_t)(((g & 1) * 8 + r) * TSTR2 + (g >> 1) * 16);
    const uint32_t boff = (uint32_t)(((g >> 1) * 8 + r) * TSTR2 + (g & 1) * 16);

    const char* gA0 = (const char*)A  + (size_t)bm * ROWA;
    const char* gB0 = (const char*)Bm + (size_t)bn * ROWB;

    #define LOADCHUNK(kc, buf) do {                                            \
        int ac_ = (kc) < 32 ? (kc) : (kc) - 32;   /* A seg2 == seg0 */         \
        uint32_t b0 = sb + (buf) * STG2;                                       \
        _Pragma("unroll")                                                      \
        for (int i_ = 0; i_ < 4; i_++) {                                       \
            int idx_ = tid + i_ * 256;                                         \
            int row_ = idx_ >> 3, c_ = idx_ & 7;                               \
            cp16(b0 + (uint32_t)(row_ * TSTR2 + c_ * 16),                      \
                 gA0 + (size_t)row_ * ROWA + ac_ * 128 + c_ * 16);             \
            cp16(b0 + TILE2 + (uint32_t)(row_ * TSTR2 + c_ * 16),              \
                 gB0 + (size_t)row_ * ROWB + (size_t)(kc) * 128 + c_ * 16);    \
        }                                                                      \
        asm volatile("cp.async.commit_group;" ::: "memory");                   \
    } while (0)

    float acc[4][4][4];
    #pragma unroll
    for (int mt = 0; mt < 4; mt++)
        #pragma unroll
        for (int nt = 0; nt < 4; nt++)
            #pragma unroll
            for (int i = 0; i < 4; i++) acc[mt][nt][i] = 0.f;

    LOADCHUNK(0, 0);

    for (int c = 0; c < NCHU; c++) {
        asm volatile("cp.async.wait_group 0;" ::: "memory");
        __syncthreads();
        if (c + 1 < NCHU) LOADCHUNK(c + 1, (c + 1) & 1);

        const uint32_t sAb = sb + (c & 1) * STG2;
        const uint32_t sBb = sAb + TILE2;
        #pragma unroll
        for (int ks = 0; ks < 4; ks++) {
            uint32_t a[4][4];
            #pragma unroll
            for (int mt = 0; mt < 4; mt++)
                ldsm4(a[mt][0], a[mt][1], a[mt][2], a[mt][3],
                      sAb + (uint32_t)((wm + mt * 16) * TSTR2 + ks * 32) + aoff);
            uint32_t b[4][2];
            #pragma unroll
            for (int nh = 0; nh < 2; nh++) {
                uint32_t r0, r1, r2, r3;
                ldsm4(r0, r1, r2, r3,
                      sBb + (uint32_t)((wn + nh * 16) * TSTR2 + ks * 32) + boff);
                b[nh*2+0][0] = r0; b[nh*2+0][1] = r1;
                b[nh*2+1][0] = r2; b[nh*2+1][1] = r3;
            }
            #pragma unroll
            for (int mt = 0; mt < 4; mt++)
                #pragma unroll
                for (int nt = 0; nt < 4; nt++)
                    mma16816(acc[mt][nt], a[mt], b[nt]);
        }
    }

    __syncthreads();   // protect smem before exit (none needed, cheap)

    // ------------------------------- epilogue --------------------------------
    const int mrow = bm + wm + (lid >> 2);
    const int ncol = bn + wn + (lid & 3) * 2;
    #pragma unroll
    for (int mt = 0; mt < 4; mt++) {
        #pragma unroll
        for (int half = 0; half < 2; half++) {
            int m = mrow + mt * 16 + half * 8;
            #pragma unroll
            for (int nt = 0; nt < 4; nt++) {
                int col = ncol + nt * 8;
                float vx = acc[mt][nt][half * 2 + 0] + bias[col];
                float vy = acc[mt][nt][half * 2 + 1] + bias[col + 1];
                if (MODE == 0) {
                    const int which = bn >> 10;          // uniform per block
                    int ccv = col & 1023;
                    int hh = ccv >> 6, d = ccv & 63;
                    int bb = m >> 11, t = m & 2047;
                    int bh = bb * H_ + hh;
                    if (which == 0) {                    // Q: pre-scale by 1/sqrt(64)
                        vx *= 0.125f; vy *= 0.125f;
                        uint32_t hi2 = pk_bf2(vx, vy);
                        uint32_t lo2 = pk_bf2(vx - bf2_lo(hi2), vy - bf2_hi(hi2));
                        size_t idx = ((size_t)bh * T_ + t) * 128 + d;
                        *(uint32_t*)&g_Qs[idx]      = hi2;
                        *(uint32_t*)&g_Qs[idx + 64] = lo2;
                    } else if (which == 1) {             // K
                        uint32_t hi2 = pk_bf2(vx, vy);
                        uint32_t lo2 = pk_bf2(vx - bf2_lo(hi2), vy - bf2_hi(hi2));
                        size_t idx = ((size_t)bh * T_ + t) * 128 + d;
                        *(uint32_t*)&g_Ks[idx]      = hi2;
                        *(uint32_t*)&g_Ks[idx + 64] = lo2;
                    } else {                             // V -> transposed split
                        uint32_t hi2 = pk_bf2(vx, vy);
                        uint32_t lo2 = pk_bf2(vx - bf2_lo(hi2), vy - bf2_hi(hi2));
                        size_t rb = (size_t)bh * 128;
                        g_Vt[(rb + d         ) * T_ + t] = (unsigned short)(hi2 & 0xffff);
                        g_Vt[(rb + d + 1     ) * T_ + t] = (unsigned short)(hi2 >> 16);
                        g_Vt[(rb + 64 + d    ) * T_ + t] = (unsigned short)(lo2 & 0xffff);
                        g_Vt[(rb + 64 + d + 1) * T_ + t] = (unsigned short)(lo2 >> 16);
                    }
                } else {
                    float2 v; v.x = vx; v.y = vy;
                    *(float2*)&Cout[(size_t)m * 1024 + col] = v;
                }
            }
        }
    }
    #undef LOADCHUNK
}

// ------------------- flash attention (tensor core, bf16 split) ---------------
#define QSTR    272                      // smem row stride bytes (136 bf16)
#define FK_TILE (64 * QSTR)              // 17408
#define FLASH_SMEM (128 * QSTR + 4 * FK_TILE)   // 104448

__global__ __launch_bounds__(128) void flash_mma_kernel()
{
    extern __shared__ char fsm[];
    const uint32_t sQ  = s2u(fsm);
    const uint32_t sK0 = sQ + 128 * QSTR;
    const uint32_t sV0 = sK0 + 2 * FK_TILE;

    const int tid = threadIdx.x, wid = tid >> 5, lid = tid & 31;
    const int qb = blockIdx.x * 128, h = blockIdx.y, b = blockIdx.z;
    const int bh = b * H_ + h;
    const int qwb = qb + wid * 32;

    const char* Qg = (const char*)(g_Qs + ((size_t)bh * T_ + qb) * 128);
    const char* Kg = (const char*)(g_Ks + ((size_t)bh * T_) * 128);
    const char* Vg = (const char*)(g_Vt + (size_t)bh * 128 * T_);

    // Q tile (128 rows x 256B) -> smem
    #pragma unroll
    for (int i = 0; i < 16; i++) {
        int idx = tid + i * 128, row = idx >> 4, c16 = idx & 15;
        cp16(sQ + row * QSTR + c16 * 16, Qg + row * 256 + c16 * 16);
    }
    asm volatile("cp.async.commit_group;" ::: "memory");

    #define LOADKV(kb_, buf_) do {                                               \
        uint32_t sk = sK0 + (buf_) * FK_TILE, sv = sV0 + (buf_) * FK_TILE;       \
        _Pragma("unroll")                                                        \
        for (int i_ = 0; i_ < 8; i_++) {                                         \
            int idx = tid + i_ * 128, row = idx >> 4, c16 = idx & 15;            \
            cp16(sk + row * QSTR + c16 * 16,                                     \
                 Kg + (size_t)((kb_) + row) * 256 + c16 * 16);                   \
            int seg = c16 >> 3, kc = c16 & 7;                                    \
            cp16(sv + row * QSTR + c16 * 16,                                     \
                 Vg + (size_t)(seg * 64 + row) * 4096 + (size_t)(kb_) * 2 + kc * 16); \
        }                                                                        \
        asm volatile("cp.async.commit_group;" ::: "memory");                     \
    } while (0)

    LOADKV(0, 0);

    const int g = lid >> 3, r = lid & 7;
    const uint32_t aoff  = (uint32_t)(((g & 1) * 8 + r) * QSTR + (g >> 1) * 16);
    const uint32_t boff  = (uint32_t)(((g >> 1) * 8 + r) * QSTR + (g & 1) * 16);
    const uint32_t qwoff = (uint32_t)(wid * 32) * QSTR;

    float O[2][8][4];
    #pragma unroll
    for (int mt = 0; mt < 2; mt++)
        #pragma unroll
        for (int nt = 0; nt < 8; nt++)
            #pragma unroll
            for (int i = 0; i < 4; i++) O[mt][nt][i] = 0.f;
    float mrow[2][2] = {{-1e30f, -1e30f}, {-1e30f, -1e30f}};
    float lrow[2][2] = {{0.f, 0.f}, {0.f, 0.f}};

    const int ntiles = (qb + 128) >> 6;

    for (int t = 0; t < ntiles; t++) {
        const int kb = t << 6;
        asm volatile("cp.async.wait_group 0;" ::: "memory");
        __syncthreads();
        if (t + 1 < ntiles) LOADKV((t + 1) << 6, (t + 1) & 1);

        if (kb <= qwb + 31) {
            const uint32_t sK = sK0 + (t & 1) * FK_TILE;
            const uint32_t sV = sV0 + (t & 1) * FK_TILE;

            // ---- S = Q . K^T (3-term split) ----
            float S[2][8][4];
            #pragma unroll
            for (int mt = 0; mt < 2; mt++)
                #pragma unroll
                for (int nt = 0; nt < 8; nt++)
                    #pragma unroll
                    for (int i = 0; i < 4; i++) S[mt][nt][i] = 0.f;

            #pragma unroll
            for (int pass = 0; pass < 3; pass++) {
                const uint32_t aseg = (pass == 1) ? 128u : 0u;   // Q lo segment
                const uint32_t bseg = (pass == 2) ? 128u : 0u;   // K lo segment
                #pragma unroll
                for (int kt = 0; kt < 4; kt++) {
                    uint32_t a0[4], a1[4];
                    ldsm4(a0[0], a0[1], a0[2], a0[3],
                          sQ + qwoff + aseg + kt * 32 + aoff);
                    ldsm4(a1[0], a1[1], a1[2], a1[3],
                          sQ + qwoff + 16 * QSTR + aseg + kt * 32 + aoff);
                    #pragma unroll
                    for (int np = 0; np < 4; np++) {
                        uint32_t b0, b1, b2, b3;
                        ldsm4(b0, b1, b2, b3,
                              sK + (uint32_t)(np * 16) * QSTR + bseg + kt * 32 + boff);
                        uint32_t bb0[2] = {b0, b1}, bb1[2] = {b2, b3};
                        mma16816(S[0][np * 2 + 0], a0, bb0);
                        mma16816(S[0][np * 2 + 1], a0, bb1);
                        mma16816(S[1][np * 2 + 0], a1, bb0);
                        mma16816(S[1][np * 2 + 1], a1, bb1);
                    }
                }
            }

            // ---- causal mask ----
            if (kb + 63 > qwb) {
                #pragma unroll
                for (int mt = 0; mt < 2; mt++) {
                    int q0 = qwb + mt * 16 + (lid >> 2);
                    #pragma unroll
                    for (int nt = 0; nt < 8; nt++) {
                        int key = kb + nt * 8 + (lid & 3) * 2;
                        if (key     > q0)     S[mt][nt][0] = -1e30f;
                        if (key + 1 > q0)     S[mt][nt][1] = -1e30f;
                        if (key     > q0 + 8) S[mt][nt][2] = -1e30f;
                        if (key + 1 > q0 + 8) S[mt][nt][3] = -1e30f;
                    }
                }
            }

            // ---- online softmax + P split ----
            uint32_t phi[2][4][4], plo[2][4][4];
            #pragma unroll
            for (int mt = 0; mt < 2; mt++) {
                float mn0 = -1e30f, mn1 = -1e30f;
                #pragma unroll
                for (int nt = 0; nt < 8; nt++) {
                    mn0 = fmaxf(mn0, fmaxf(S[mt][nt][0], S[mt][nt][1]));
                    mn1 = fmaxf(mn1, fmaxf(S[mt][nt][2], S[mt][nt][3]));
                }
                mn0 = fmaxf(mn0, __shfl_xor_sync(0xffffffffu, mn0, 1));
                mn0 = fmaxf(mn0, __shfl_xor_sync(0xffffffffu, mn0, 2));
                mn1 = fmaxf(mn1, __shfl_xor_sync(0xffffffffu, mn1, 1));
                mn1 = fmaxf(mn1, __shfl_xor_sync(0xffffffffu, mn1, 2));
                float mx0 = fmaxf(mrow[mt][0], mn0), mx1 = fmaxf(mrow[mt][1], mn1);
                float al0 = __expf(mrow[mt][0] - mx0), al1 = __expf(mrow[mt][1] - mx1);
                mrow[mt][0] = mx0; mrow[mt][1] = mx1;
                float s0 = 0.f, s1 = 0.f;
                #pragma unroll
                for (int nt = 0; nt < 8; nt++) {
                    float p0 = __expf(S[mt][nt][0] - mx0);
                    float p1 = __expf(S[mt][nt][1] - mx0);
                    float p2 = __expf(S[mt][nt][2] - mx1);
                    float p3 = __expf(S[mt][nt][3] - mx1);
                    s0 += p0 + p1; s1 += p2 + p3;
                    S[mt][nt][0] = p0; S[mt][nt][1] = p1;
                    S[mt][nt][2] = p2; S[mt][nt][3] = p3;
                }
                s0 += __shfl_xor_sync(0xffffffffu, s0, 1);
                s0 += __shfl_xor_sync(0xffffffffu, s0, 2);
                s1 += __shfl_xor_sync(0xffffffffu, s1, 1);
                s1 += __shfl_xor_sync(0xffffffffu, s1, 2);
                lrow[mt][0] = lrow[mt][0] * al0 + s0;
                lrow[mt][1] = lrow[mt][1] * al1 + s1;
                #pragma unroll
                for (int nt = 0; nt < 8; nt++) {
                    O[mt][nt][0] *= al0; O[mt][nt][1] *= al0;
                    O[mt][nt][2] *= al1; O[mt][nt][3] *= al1;
                }
                // pack P fragments: C-frag(ntiles 2kt,2kt+1) -> A-frag(k16 tile kt)
                #pragma unroll
                for (int kt = 0; kt < 4; kt++) {
                    uint32_t h0 = pk_bf2(S[mt][2*kt  ][0], S[mt][2*kt  ][1]);
                    uint32_t h1 = pk_bf2(S[mt][2*kt  ][2], S[mt][2*kt  ][3]);
                    uint32_t h2 = pk_bf2(S[mt][2*kt+1][0], S[mt][2*kt+1][1]);
                    uint32_t h3 = pk_bf2(S[mt][2*kt+1][2], S[mt][2*kt+1][3]);
                    phi[mt][kt][0] = h0; phi[mt][kt][1] = h1;
                    phi[mt][kt][2] = h2; phi[mt][kt][3] = h3;
                    plo[mt][kt][0] = pk_bf2(S[mt][2*kt  ][0] - bf2_lo(h0),
                                            S[mt][2*kt  ][1] - bf2_hi(h0));
                    plo[mt][kt][1] = pk_bf2(S[mt][2*kt  ][2] - bf2_lo(h1),
                                            S[mt][2*kt  ][3] - bf2_hi(h1));
                    plo[mt][kt][2] = pk_bf2(S[mt][2*kt+1][0] - bf2_lo(h2),
                                            S[mt][2*kt+1][1] - bf2_hi(h2));
                    plo[mt][kt][3] = pk_bf2(S[mt][2*kt+1][2] - bf2_lo(h3),
                                            S[mt][2*kt+1][3] - bf2_hi(h3));
                }
            }

            // ---- O += P . V (3-term split: Phi*Vhi + Plo*Vhi + Phi*Vlo) ----
            #pragma unroll
            for (int pass = 0; pass < 3; pass++) {
                const uint32_t bcol = (pass == 2) ? 128u : 0u;   // V lo columns
                #pragma unroll
                for (int kt = 0; kt < 4; kt++) {
                    const uint32_t* A0 = (pass == 1) ? plo[0][kt] : phi[0][kt];
                    const uint32_t* A1 = (pass == 1) ? plo[1][kt] : phi[1][kt];
                    #pragma unroll
                    for (int np = 0; np < 4; np++) {
                        uint32_t b0, b1, b2, b3;
                        ldsm4(b0, b1, b2, b3,
                              sV + (uint32_t)(np * 16) * QSTR + bcol + kt * 32 + boff);
                        uint32_t bb0[2] = {b0, b1}, bb1[2] = {b2, b3};
                        mma16816(O[0][np * 2 + 0], A0, bb0);
                        mma16816(O[0][np * 2 + 1], A0, bb1);
                        mma16816(O[1][np * 2 + 0], A1, bb0);
                        mma16816(O[1][np * 2 + 1], A1, bb1);
                    }
                }
            }
        }
    }

    // ---- normalize + write ----
    #pragma unroll
    for (int mt = 0; mt < 2; mt++) {
        float inv0 = 1.f / lrow[mt][0], inv1 = 1.f / lrow[mt][1];
        int q0 = qwb + mt * 16 + (lid >> 2);
        float* o0 = g_O + ((size_t)b * T_ + q0) * C_ + h * 64 + (lid & 3) * 2;
        float* o1 = o0 + 8 * C_;
        #pragma unroll
        for (int nt = 0; nt < 8; nt++) {
            float2 v0, v1;
            v0.x = O[mt][nt][0] * inv0; v0.y = O[mt][nt][1] * inv0;
            v1.x = O[mt][nt][2] * inv1; v1.y = O[mt][nt][3] * inv1;
            *(float2*)(o0 + nt * 8) = v0;
            *(float2*)(o1 + nt * 8) = v1;
        }
    }
    #undef LOADKV
}

// ------------------------------- launcher -----------------------------------
extern "C" void kernel_launch(void* const* d_in, const int* in_sizes, int n_in,
                              void* d_out, int out_size) {
    const float* x    = (const float*)d_in[0];   // [4,2048,1024]
    const float* Wqkv = (const float*)d_in[1];   // [1024,3072]
    const float* bqkv = (const float*)d_in[2];   // [3072]
    const float* Wout = (const float*)d_in[3];   // [1024,1024]
    const float* bout = (const float*)d_in[4];   // [1024]
    float* out = (float*)d_out;                  // [4,2048,1024]

    cudaFuncSetAttribute(flash_mma_kernel,
                         cudaFuncAttributeMaxDynamicSharedMemorySize, FLASH_SMEM);
    cudaFuncSetAttribute(gemm_mma_kernel<0>,
                         cudaFuncAttributeMaxDynamicSharedMemorySize, GSMEM);
    cudaFuncSetAttribute(gemm_mma_kernel<1>,
                         cudaFuncAttributeMaxDynamicSharedMemorySize, GSMEM);

    unsigned short* gA  = nullptr; cudaGetSymbolAddress((void**)&gA,  g_A);
    unsigned short* gBq = nullptr; cudaGetSymbolAddress((void**)&gBq, g_Bq);
    unsigned short* gBo = nullptr; cudaGetSymbolAddress((void**)&gBo, g_Bo);
    float* gO = nullptr; cudaGetSymbolAddress((void**)&gO, g_O);

    // 1) split/transpose prep
    prep_split_kernel<<<8192, 256>>>(x, gA);
    prep_wsplit_kernel<3072><<<dim3(96, 32), dim3(32, 8)>>>(Wqkv, gBq);
    prep_wsplit_kernel<1024><<<dim3(32, 32), dim3(32, 8)>>>(Wout, gBo);

    // 2) QKV projection -> split bf16 Q/K/V^T (head-major)
    gemm_mma_kernel<0><<<dim3(24, 64), 256, GSMEM>>>(gA, gBq, bqkv, nullptr);

    // 3) causal flash attention (tensor cores) -> g_O [B,T,C]
    flash_mma_kernel<<<dim3(16, 16, 4), 128, FLASH_SMEM>>>();

    // 4) split g_O, output projection -> d_out
    prep_split_kernel<<<8192, 256>>>(gO, gA);
    gemm_mma_kernel<1><<<dim3(8, 64), 256, GSMEM>>>(gA, gBo, bout, out);
}

// round 10
// speedup vs baseline: 2.7319x; 1.0034x over previous
#include <cuda_runtime.h>
#include <cuda_bf16.h>
#include <cstdint>

#define B_   4
#define T_   2048
#define C_   1024
#define H_   16
#define D_   64
#define BT_  (B_*T_)
#define BH_  (B_*H_)
#define K3_  3072     // logical 3-segment K for projections
#define K2_  2048     // A stored as [hi|lo] only (seg2 == seg0)

// ------------------------- scratch (device globals) -------------------------
__device__ __align__(16) float g_O[BT_*C_];                  // [B][T][C]
__device__ __align__(16) unsigned short g_A [BT_*K2_];       // x-split / O-split [hi|lo]
__device__ __align__(16) unsigned short g_Bq[3*C_*K3_];      // Wqkv^T split [hi|hi|lo]
__device__ __align__(16) unsigned short g_Bo[C_*K3_];        // Wout^T split [hi|hi|lo]
__device__ __align__(16) unsigned short g_Qs[BH_*T_*128];    // [bh][t][hi64|lo64], Q pre-scaled
__device__ __align__(16) unsigned short g_Ks[BH_*T_*128];    // [bh][t][hi64|lo64]
__device__ __align__(16) unsigned short g_Vt[BH_*128*T_];    // [bh][hi d0..63, lo d0..63][t]

// ------------------------------ small helpers -------------------------------
__device__ __forceinline__ uint32_t s2u(const void* p) {
    uint32_t a;
    asm("{ .reg .u64 t; cvta.to.shared.u64 t, %1; cvt.u32.u64 %0, t; }" : "=r"(a) : "l"(p));
    return a;
}
__device__ __forceinline__ void cp16(uint32_t d, const void* s) {
    asm volatile("cp.async.cg.shared.global [%0], [%1], 16;" :: "r"(d), "l"(s));
}
__device__ __forceinline__ void ldsm4(uint32_t& r0, uint32_t& r1, uint32_t& r2, uint32_t& r3,
                                      uint32_t a) {
    asm volatile("ldmatrix.sync.aligned.m8n8.x4.shared.b16 {%0,%1,%2,%3}, [%4];"
                 : "=r"(r0), "=r"(r1), "=r"(r2), "=r"(r3) : "r"(a));
}
__device__ __forceinline__ void mma16816(float* c, const uint32_t* a, const uint32_t* b) {
    asm volatile("mma.sync.aligned.m16n8k16.row.col.f32.bf16.bf16.f32 "
                 "{%0,%1,%2,%3}, {%4,%5,%6,%7}, {%8,%9}, {%0,%1,%2,%3};"
                 : "+f"(c[0]), "+f"(c[1]), "+f"(c[2]), "+f"(c[3])
                 : "r"(a[0]), "r"(a[1]), "r"(a[2]), "r"(a[3]), "r"(b[0]), "r"(b[1]));
}
// pack two floats into bf16x2: low half = first arg
__device__ __forceinline__ uint32_t pk_bf2(float lo, float hi) {
    uint32_t d;
    asm("cvt.rn.bf16x2.f32 %0, %1, %2;" : "=r"(d) : "f"(hi), "f"(lo));
    return d;
}
__device__ __forceinline__ float bf2_lo(uint32_t u) { return __uint_as_float(u << 16); }
__device__ __forceinline__ float bf2_hi(uint32_t u) { return __uint_as_float(u & 0xffff0000u); }

// ------------------------------ prep kernels --------------------------------
// split fp32 [rows][1024] -> bf16 [rows][2048] = [hi | lo]
__global__ __launch_bounds__(256) void prep_split_kernel(
    const float* __restrict__ src, unsigned short* __restrict__ dst)
{
    int idx = blockIdx.x * 256 + threadIdx.x;
    int row = idx >> 8;
    int c4  = idx & 255;
    float4 v = *(const float4*)(src + (size_t)row * 1024 + c4 * 4);
    float f[4] = {v.x, v.y, v.z, v.w};
    unsigned short h[4], l[4];
    #pragma unroll
    for (int i = 0; i < 4; i++) {
        __nv_bfloat16 hb = __float2bfloat16(f[i]);
        __nv_bfloat16 lb = __float2bfloat16(f[i] - __bfloat162float(hb));
        h[i] = __bfloat16_as_ushort(hb);
        l[i] = __bfloat16_as_ushort(lb);
    }
    uint64_t hp = (uint64_t)h[0] | ((uint64_t)h[1] << 16) | ((uint64_t)h[2] << 32) | ((uint64_t)h[3] << 48);
    uint64_t lp = (uint64_t)l[0] | ((uint64_t)l[1] << 16) | ((uint64_t)l[2] << 32) | ((uint64_t)l[3] << 48);
    unsigned short* rp = dst + (size_t)row * K2_ + c4 * 4;
    *(uint64_t*)(rp)        = hp;
    *(uint64_t*)(rp + 1024) = lp;
}

// transpose + split: W[1024][N] fp32 -> dst[N][3072] = [hi | hi | lo]
template<int N>
__global__ __launch_bounds__(256) void prep_wsplit_kernel(
    const float* __restrict__ W, unsigned short* __restrict__ dst)
{
    __shared__ float tile[32][33];
    int n0 = blockIdx.x * 32, k0 = blockIdx.y * 32;
    int tx = threadIdx.x, ty = threadIdx.y;
    #pragma unroll
    for (int i = 0; i < 32; i += 8)
        tile[ty + i][tx] = W[(size_t)(k0 + ty + i) * N + n0 + tx];
    __syncthreads();
    #pragma unroll
    for (int i = 0; i < 32; i += 8) {
        int n = n0 + ty + i;
        int k = k0 + tx;
        float v = tile[tx][ty + i];
        __nv_bfloat16 hb = __float2bfloat16(v);
        __nv_bfloat16 lb = __float2bfloat16(v - __bfloat162float(hb));
        unsigned short hu = __bfloat16_as_ushort(hb);
        unsigned short lu = __bfloat16_as_ushort(lb);
        unsigned short* rp = dst + (size_t)n * K3_ + k;
        rp[0]    = hu;
        rp[1024] = hu;
        rp[2048] = lu;
    }
}

// ---------------------- mma.sync bf16 GEMM (tensor core) ---------------------
// D[128,128] = A[128, K2 as 3-seg] . B[128, K3]^T, K-chunk 64, 3-stage, 1 sync/chunk.
#define KCH   64
#define TSTR2 144                        // bytes per 64-k row (128 B + 16 pad)
#define TILE2 (128 * TSTR2)              // 18432
#define STG2  (2 * TILE2)                // A+B per stage = 36864
#define GSMEM (3 * STG2)                 // 110592 (3-stage)
#define NCHU  (K3_ / KCH)                // 48
#define ROWA  (K2_ * 2)                  // 4096 B
#define ROWB  (K3_ * 2)                  // 6144 B

template<int MODE>
__global__ __launch_bounds__(256, 2) void gemm_mma_kernel(
    const unsigned short* __restrict__ A, const unsigned short* __restrict__ Bm,
    const float* __restrict__ bias, float* __restrict__ Cout)
{
    extern __shared__ __align__(128) char smem[];
    const uint32_t sb = s2u(smem);

    const int tid = threadIdx.x, wid = tid >> 5, lid = tid & 31;
    const int bm = blockIdx.y * 128, bn = blockIdx.x * 128;
    const int wm = (wid & 1) * 64, wn = (wid >> 1) * 32;

    const int g = lid >> 3, r = lid & 7;
    const uint32_t aoff = (uint32_t)(((g & 1) * 8 + r) * TSTR2 + (g >> 1) * 16);
    const uint32_t boff = (uint32_t)(((g >> 1) * 8 + r) * TSTR2 + (g & 1) * 16);

    const char* gA0 = (const char*)A  + (size_t)bm * ROWA;
    const char* gB0 = (const char*)Bm + (size_t)bn * ROWB;

    #define LOADCHUNK(kc, buf) do {                                            \
        int ac_ = (kc) < 32 ? (kc) : (kc) - 32;   /* A seg2 == seg0 */         \
        uint32_t b0 = sb + (buf) * STG2;                                       \
        _Pragma("unroll")                                                      \
        for (int i_ = 0; i_ < 4; i_++) {                                       \
            int idx_ = tid + i_ * 256;                                         \
            int row_ = idx_ >> 3, c_ = idx_ & 7;                               \
            cp16(b0 + (uint32_t)(row_ * TSTR2 + c_ * 16),                      \
                 gA0 + (size_t)row_ * ROWA + ac_ * 128 + c_ * 16);             \
            cp16(b0 + TILE2 + (uint32_t)(row_ * TSTR2 + c_ * 16),              \
                 gB0 + (size_t)row_ * ROWB + (size_t)(kc) * 128 + c_ * 16);    \
        }                                                                      \
        asm volatile("cp.async.commit_group;" ::: "memory");                   \
    } while (0)

    float acc[4][4][4];
    #pragma unroll
    for (int mt = 0; mt < 4; mt++)
        #pragma unroll
        for (int nt = 0; nt < 4; nt++)
            #pragma unroll
            for (int i = 0; i < 4; i++) acc[mt][nt][i] = 0.f;

    LOADCHUNK(0, 0);
    LOADCHUNK(1, 1);

    int buf = 0;
    for (int c = 0; c < NCHU; c++) {
        if (c + 1 < NCHU) {
            asm volatile("cp.async.wait_group 1;" ::: "memory");
        } else {
            asm volatile("cp.async.wait_group 0;" ::: "memory");
        }
        __syncthreads();
        if (c + 2 < NCHU) {
            int nb = buf + 2; if (nb >= 3) nb -= 3;
            LOADCHUNK(c + 2, nb);
        }

        const uint32_t sAb = sb + buf * STG2;
        const uint32_t sBb = sAb + TILE2;
        #pragma unroll
        for (int ks = 0; ks < 4; ks++) {
            uint32_t a[4][4];
            #pragma unroll
            for (int mt = 0; mt < 4; mt++)
                ldsm4(a[mt][0], a[mt][1], a[mt][2], a[mt][3],
                      sAb + (uint32_t)((wm + mt * 16) * TSTR2 + ks * 32) + aoff);
            uint32_t b[4][2];
            #pragma unroll
            for (int nh = 0; nh < 2; nh++) {
                uint32_t r0, r1, r2, r3;
                ldsm4(r0, r1, r2, r3,
                      sBb + (uint32_t)((wn + nh * 16) * TSTR2 + ks * 32) + boff);
                b[nh*2+0][0] = r0; b[nh*2+0][1] = r1;
                b[nh*2+1][0] = r2; b[nh*2+1][1] = r3;
            }
            #pragma unroll
            for (int mt = 0; mt < 4; mt++)
                #pragma unroll
                for (int nt = 0; nt < 4; nt++)
                    mma16816(acc[mt][nt], a[mt], b[nt]);
        }
        buf++; if (buf >= 3) buf = 0;
    }

    // ------------------------------- epilogue --------------------------------
    const int mrow = bm + wm + (lid >> 2);
    const int ncol = bn + wn + (lid & 3) * 2;
    #pragma unroll
    for (int mt = 0; mt < 4; mt++) {
        #pragma unroll
        for (int half = 0; half < 2; half++) {
            int m = mrow + mt * 16 + half * 8;
            #pragma unroll
            for (int nt = 0; nt < 4; nt++) {
                int col = ncol + nt * 8;
                float vx = acc[mt][nt][half * 2 + 0] + bias[col];
                float vy = acc[mt][nt][half * 2 + 1] + bias[col + 1];
                if (MODE == 0) {
                    const int which = bn >> 10;          // uniform per block
                    int ccv = col & 1023;
                    int hh = ccv >> 6, d = ccv & 63;
                    int bb = m >> 11, t = m & 2047;
                    int bh = bb * H_ + hh;
                    if (which == 0) {                    // Q: pre-scale by 1/sqrt(64)
                        vx *= 0.125f; vy *= 0.125f;
                        uint32_t hi2 = pk_bf2(vx, vy);
                        uint32_t lo2 = pk_bf2(vx - bf2_lo(hi2), vy - bf2_hi(hi2));
                        size_t idx = ((size_t)bh * T_ + t) * 128 + d;
                        *(uint32_t*)&g_Qs[idx]      = hi2;
                        *(uint32_t*)&g_Qs[idx + 64] = lo2;
                    } else if (which == 1) {             // K
                        uint32_t hi2 = pk_bf2(vx, vy);
                        uint32_t lo2 = pk_bf2(vx - bf2_lo(hi2), vy - bf2_hi(hi2));
                        size_t idx = ((size_t)bh * T_ + t) * 128 + d;
                        *(uint32_t*)&g_Ks[idx]      = hi2;
                        *(uint32_t*)&g_Ks[idx + 64] = lo2;
                    } else {                             // V -> transposed split
                        uint32_t hi2 = pk_bf2(vx, vy);
                        uint32_t lo2 = pk_bf2(vx - bf2_lo(hi2), vy - bf2_hi(hi2));
                        size_t rb = (size_t)bh * 128;
                        g_Vt[(rb + d         ) * T_ + t] = (unsigned short)(hi2 & 0xffff);
                        g_Vt[(rb + d + 1     ) * T_ + t] = (unsigned short)(hi2 >> 16);
                        g_Vt[(rb + 64 + d    ) * T_ + t] = (unsigned short)(lo2 & 0xffff);
                        g_Vt[(rb + 64 + d + 1) * T_ + t] = (unsigned short)(lo2 >> 16);
                    }
                } else {
                    float2 v; v.x = vx; v.y = vy;
                    *(float2*)&Cout[(size_t)m * 1024 + col] = v;
                }
            }
        }
    }
    #undef LOADCHUNK
}

// ------------------- flash attention (tensor core, bf16 split) ---------------
#define QSTR    272                      // smem row stride bytes (136 bf16)
#define FK_TILE (64 * QSTR)              // 17408
#define FLASH_SMEM (128 * QSTR + 4 * FK_TILE)   // 104448

__global__ __launch_bounds__(128) void flash_mma_kernel()
{
    extern __shared__ char fsm[];
    const uint32_t sQ  = s2u(fsm);
    const uint32_t sK0 = sQ + 128 * QSTR;
    const uint32_t sV0 = sK0 + 2 * FK_TILE;

    const int tid = threadIdx.x, wid = tid >> 5, lid = tid & 31;
    const int qb = blockIdx.x * 128, h = blockIdx.y, b = blockIdx.z;
    const int bh = b * H_ + h;
    const int qwb = qb + wid * 32;

    const char* Qg = (const char*)(g_Qs + ((size_t)bh * T_ + qb) * 128);
    const char* Kg = (const char*)(g_Ks + ((size_t)bh * T_) * 128);
    const char* Vg = (const char*)(g_Vt + (size_t)bh * 128 * T_);

    // Q tile (128 rows x 256B) -> smem
    #pragma unroll
    for (int i = 0; i < 16; i++) {
        int idx = tid + i * 128, row = idx >> 4, c16 = idx & 15;
        cp16(sQ + row * QSTR + c16 * 16, Qg + row * 256 + c16 * 16);
    }
    asm volatile("cp.async.commit_group;" ::: "memory");

    #define LOADKV(kb_, buf_) do {                                               \
        uint32_t sk = sK0 + (buf_) * FK_TILE, sv = sV0 + (buf_) * FK_TILE;       \
        _Pragma("unroll")                                                        \
        for (int i_ = 0; i_ < 8; i_++) {                                         \
            int idx = tid + i_ * 128, row = idx >> 4, c16 = idx & 15;            \
            cp16(sk + row * QSTR + c16 * 16,                                     \
                 Kg + (size_t)((kb_) + row) * 256 + c16 * 16);                   \
            int seg = c16 >> 3, kc = c16 & 7;                                    \
            cp16(sv + row * QSTR + c16 * 16,                                     \
                 Vg + (size_t)(seg * 64 + row) * 4096 + (size_t)(kb_) * 2 + kc * 16); \
        }                                                                        \
        asm volatile("cp.async.commit_group;" ::: "memory");                     \
    } while (0)

    LOADKV(0, 0);

    const int g = lid >> 3, r = lid & 7;
    const uint32_t aoff  = (uint32_t)(((g & 1) * 8 + r) * QSTR + (g >> 1) * 16);
    const uint32_t boff  = (uint32_t)(((g >> 1) * 8 + r) * QSTR + (g & 1) * 16);
    const uint32_t qwoff = (uint32_t)(wid * 32) * QSTR;

    float O[2][8][4];
    #pragma unroll
    for (int mt = 0; mt < 2; mt++)
        #pragma unroll
        for (int nt = 0; nt < 8; nt++)
            #pragma unroll
            for (int i = 0; i < 4; i++) O[mt][nt][i] = 0.f;
    float mrow[2][2] = {{-1e30f, -1e30f}, {-1e30f, -1e30f}};
    float lrow[2][2] = {{0.f, 0.f}, {0.f, 0.f}};

    const int ntiles = (qb + 128) >> 6;

    for (int t = 0; t < ntiles; t++) {
        const int kb = t << 6;
        asm volatile("cp.async.wait_group 0;" ::: "memory");
        __syncthreads();
        if (t + 1 < ntiles) LOADKV((t + 1) << 6, (t + 1) & 1);

        if (kb <= qwb + 31) {
            const uint32_t sK = sK0 + (t & 1) * FK_TILE;
            const uint32_t sV = sV0 + (t & 1) * FK_TILE;

            // ---- S = Q . K^T (3-term split) ----
            float S[2][8][4];
            #pragma unroll
            for (int mt = 0; mt < 2; mt++)
                #pragma unroll
                for (int nt = 0; nt < 8; nt++)
                    #pragma unroll
                    for (int i = 0; i < 4; i++) S[mt][nt][i] = 0.f;

            #pragma unroll
            for (int pass = 0; pass < 3; pass++) {
                const uint32_t aseg = (pass == 1) ? 128u : 0u;   // Q lo segment
                const uint32_t bseg = (pass == 2) ? 128u : 0u;   // K lo segment
                #pragma unroll
                for (int kt = 0; kt < 4; kt++) {
                    uint32_t a0[4], a1[4];
                    ldsm4(a0[0], a0[1], a0[2], a0[3],
                          sQ + qwoff + aseg + kt * 32 + aoff);
                    ldsm4(a1[0], a1[1], a1[2], a1[3],
                          sQ + qwoff + 16 * QSTR + aseg + kt * 32 + aoff);
                    #pragma unroll
                    for (int np = 0; np < 4; np++) {
                        uint32_t b0, b1, b2, b3;
                        ldsm4(b0, b1, b2, b3,
                              sK + (uint32_t)(np * 16) * QSTR + bseg + kt * 32 + boff);
                        uint32_t bb0[2] = {b0, b1}, bb1[2] = {b2, b3};
                        mma16816(S[0][np * 2 + 0], a0, bb0);
                        mma16816(S[0][np * 2 + 1], a0, bb1);
                        mma16816(S[1][np * 2 + 0], a1, bb0);
                        mma16816(S[1][np * 2 + 1], a1, bb1);
                    }
                }
            }

            // ---- causal mask ----
            if (kb + 63 > qwb) {
                #pragma unroll
                for (int mt = 0; mt < 2; mt++) {
                    int q0 = qwb + mt * 16 + (lid >> 2);
                    #pragma unroll
                    for (int nt = 0; nt < 8; nt++) {
                        int key = kb + nt * 8 + (lid & 3) * 2;
                        if (key     > q0)     S[mt][nt][0] = -1e30f;
                        if (key + 1 > q0)     S[mt][nt][1] = -1e30f;
                        if (key     > q0 + 8) S[mt][nt][2] = -1e30f;
                        if (key + 1 > q0 + 8) S[mt][nt][3] = -1e30f;
                    }
                }
            }

            // ---- online softmax + P split ----
            uint32_t phi[2][4][4], plo[2][4][4];
            #pragma unroll
            for (int mt = 0; mt < 2; mt++) {
                float mn0 = -1e30f, mn1 = -1e30f;
                #pragma unroll
                for (int nt = 0; nt < 8; nt++) {
                    mn0 = fmaxf(mn0, fmaxf(S[mt][nt][0], S[mt][nt][1]));
                    mn1 = fmaxf(mn1, fmaxf(S[mt][nt][2], S[mt][nt][3]));
                }
                mn0 = fmaxf(mn0, __shfl_xor_sync(0xffffffffu, mn0, 1));
                mn0 = fmaxf(mn0, __shfl_xor_sync(0xffffffffu, mn0, 2));
                mn1 = fmaxf(mn1, __shfl_xor_sync(0xffffffffu, mn1, 1));
                mn1 = fmaxf(mn1, __shfl_xor_sync(0xffffffffu, mn1, 2));
                float mx0 = fmaxf(mrow[mt][0], mn0), mx1 = fmaxf(mrow[mt][1], mn1);
                float al0 = __expf(mrow[mt][0] - mx0), al1 = __expf(mrow[mt][1] - mx1);
                mrow[mt][0] = mx0; mrow[mt][1] = mx1;
                float s0 = 0.f, s1 = 0.f;
                #pragma unroll
                for (int nt = 0; nt < 8; nt++) {
                    float p0 = __expf(S[mt][nt][0] - mx0);
                    float p1 = __expf(S[mt][nt][1] - mx0);
                    float p2 = __expf(S[mt][nt][2] - mx1);
                    float p3 = __expf(S[mt][nt][3] - mx1);
                    s0 += p0 + p1; s1 += p2 + p3;
                    S[mt][nt][0] = p0; S[mt][nt][1] = p1;
                    S[mt][nt][2] = p2; S[mt][nt][3] = p3;
                }
                s0 += __shfl_xor_sync(0xffffffffu, s0, 1);
                s0 += __shfl_xor_sync(0xffffffffu, s0, 2);
                s1 += __shfl_xor_sync(0xffffffffu, s1, 1);
                s1 += __shfl_xor_sync(0xffffffffu, s1, 2);
                lrow[mt][0] = lrow[mt][0] * al0 + s0;
                lrow[mt][1] = lrow[mt][1] * al1 + s1;
                #pragma unroll
                for (int nt = 0; nt < 8; nt++) {
                    O[mt][nt][0] *= al0; O[mt][nt][1] *= al0;
                    O[mt][nt][2] *= al1; O[mt][nt][3] *= al1;
                }
                // pack P fragments: C-frag(ntiles 2kt,2kt+1) -> A-frag(k16 tile kt)
                #pragma unroll
                for (int kt = 0; kt < 4; kt++) {
                    uint32_t h0 = pk_bf2(S[mt][2*kt  ][0], S[mt][2*kt  ][1]);
                    uint32_t h1 = pk_bf2(S[mt][2*kt  ][2], S[mt][2*kt  ][3]);
                    uint32_t h2 = pk_bf2(S[mt][2*kt+1][0], S[mt][2*kt+1][1]);
                    uint32_t h3 = pk_bf2(S[mt][2*kt+1][2], S[mt][2*kt+1][3]);
                    phi[mt][kt][0] = h0; phi[mt][kt][1] = h1;
                    phi[mt][kt][2] = h2; phi[mt][kt][3] = h3;
                    plo[mt][kt][0] = pk_bf2(S[mt][2*kt  ][0] - bf2_lo(h0),
                                            S[mt][2*kt  ][1] - bf2_hi(h0));
                    plo[mt][kt][1] = pk_bf2(S[mt][2*kt  ][2] - bf2_lo(h1),
                                            S[mt][2*kt  ][3] - bf2_hi(h1));
                    plo[mt][kt][2] = pk_bf2(S[mt][2*kt+1][0] - bf2_lo(h2),
                                            S[mt][2*kt+1][1] - bf2_hi(h2));
                    plo[mt][kt][3] = pk_bf2(S[mt][2*kt+1][2] - bf2_lo(h3),
                                            S[mt][2*kt+1][3] - bf2_hi(h3));
                }
            }

            // ---- O += P . V (3-term split: Phi*Vhi + Plo*Vhi + Phi*Vlo) ----
            #pragma unroll
            for (int pass = 0; pass < 3; pass++) {
                const uint32_t bcol = (pass == 2) ? 128u : 0u;   // V lo columns
                #pragma unroll
                for (int kt = 0; kt < 4; kt++) {
                    const uint32_t* A0 = (pass == 1) ? plo[0][kt] : phi[0][kt];
                    const uint32_t* A1 = (pass == 1) ? plo[1][kt] : phi[1][kt];
                    #pragma unroll
                    for (int np = 0; np < 4; np++) {
                        uint32_t b0, b1, b2, b3;
                        ldsm4(b0, b1, b2, b3,
                              sV + (uint32_t)(np * 16) * QSTR + bcol + kt * 32 + boff);
                        uint32_t bb0[2] = {b0, b1}, bb1[2] = {b2, b3};
                        mma16816(O[0][np * 2 + 0], A0, bb0);
                        mma16816(O[0][np * 2 + 1], A0, bb1);
                        mma16816(O[1][np * 2 + 0], A1, bb0);
                        mma16816(O[1][np * 2 + 1], A1, bb1);
                    }
                }
            }
        }
    }

    // ---- normalize + write ----
    #pragma unroll
    for (int mt = 0; mt < 2; mt++) {
        float inv0 = 1.f / lrow[mt][0], inv1 = 1.f / lrow[mt][1];
        int q0 = qwb + mt * 16 + (lid >> 2);
        float* o0 = g_O + ((size_t)b * T_ + q0) * C_ + h * 64 + (lid & 3) * 2;
        float* o1 = o0 + 8 * C_;
        #pragma unroll
        for (int nt = 0; nt < 8; nt++) {
            float2 v0, v1;
            v0.x = O[mt][nt][0] * inv0; v0.y = O[mt][nt][1] * inv0;
            v1.x = O[mt][nt][2] * inv1; v1.y = O[mt][nt][3] * inv1;
            *(float2*)(o0 + nt * 8) = v0;
            *(float2*)(o1 + nt * 8) = v1;
        }
    }
    #undef LOADKV
}

// ------------------------------- launcher -----------------------------------
extern "C" void kernel_launch(void* const* d_in, const int* in_sizes, int n_in,
                              void* d_out, int out_size) {
    const float* x    = (const float*)d_in[0];   // [4,2048,1024]
    const float* Wqkv = (const float*)d_in[1];   // [1024,3072]
    const float* bqkv = (const float*)d_in[2];   // [3072]
    const float* Wout = (const float*)d_in[3];   // [1024,1024]
    const float* bout = (const float*)d_in[4];   // [1024]
    float* out = (float*)d_out;                  // [4,2048,1024]

    cudaFuncSetAttribute(flash_mma_kernel,
                         cudaFuncAttributeMaxDynamicSharedMemorySize, FLASH_SMEM);
    cudaFuncSetAttribute(gemm_mma_kernel<0>,
                         cudaFuncAttributeMaxDynamicSharedMemorySize, GSMEM);
    cudaFuncSetAttribute(gemm_mma_kernel<1>,
                         cudaFuncAttributeMaxDynamicSharedMemorySize, GSMEM);

    unsigned short* gA  = nullptr; cudaGetSymbolAddress((void**)&gA,  g_A);
    unsigned short* gBq = nullptr; cudaGetSymbolAddress((void**)&gBq, g_Bq);
    unsigned short* gBo = nullptr; cudaGetSymbolAddress((void**)&gBo, g_Bo);
    float* gO = nullptr; cudaGetSymbolAddress((void**)&gO, g_O);

    // 1) split/transpose prep
    prep_split_kernel<<<8192, 256>>>(x, gA);
    prep_wsplit_kernel<3072><<<dim3(96, 32), dim3(32, 8)>>>(Wqkv, gBq);
    prep_wsplit_kernel<1024><<<dim3(32, 32), dim3(32, 8)>>>(Wout, gBo);

    // 2) QKV projection -> split bf16 Q/K/V^T (head-major)
    gemm_mma_kernel<0><<<dim3(24, 64), 256, GSMEM>>>(gA, gBq, bqkv, nullptr);

    // 3) causal flash attention (tensor cores) -> g_O [B,T,C]
    flash_mma_kernel<<<dim3(16, 16, 4), 128, FLASH_SMEM>>>();

    // 4) split g_O, output projection -> d_out
    prep_split_kernel<<<8192, 256>>>(gO, gA);
    gemm_mma_kernel<1><<<dim3(8, 64), 256, GSMEM>>>(gA, gBo, bout, out);
}